// round 2
// baseline (speedup 1.0000x reference)
#include <cuda_runtime.h>

#define Bn 8
#define Tt 64
#define Nn 128
#define Dd 128
#define TWw 62

// scratch (allocation-free rule: __device__ globals)
__device__ float g_wf[Bn * Tt * Nn * Dd];   // gated + L2-normalized feat
__device__ float g_P[Bn * Tt * Dd];         // per-(b,t) node-sum of wf

// ---------------------------------------------------------------------------
// Kernel 1: wf = (feat * sigmoid(w)) / max(||.||2, 1e-12), one warp per row
// ---------------------------------------------------------------------------
__global__ __launch_bounds__(256) void wf_kernel(const float* __restrict__ feat,
                                                 const float* __restrict__ w) {
    __shared__ float sigw[Dd];
    int tid = threadIdx.x;
    if (tid < Dd) sigw[tid] = 1.0f / (1.0f + expf(-w[tid]));
    __syncthreads();

    int warp = tid >> 5, lane = tid & 31;
    size_t row = (size_t)blockIdx.x * 8 + warp;          // 65536 rows total
    const float4* src = (const float4*)(feat + row * Dd);
    float4 v = src[lane];
    float4 sw = ((const float4*)sigw)[lane];
    v.x *= sw.x; v.y *= sw.y; v.z *= sw.z; v.w *= sw.w;
    float sq = v.x * v.x + v.y * v.y + v.z * v.z + v.w * v.w;
#pragma unroll
    for (int off = 16; off; off >>= 1) sq += __shfl_xor_sync(0xffffffffu, sq, off);
    float scale = 1.0f / fmaxf(sqrtf(sq), 1e-12f);
    v.x *= scale; v.y *= scale; v.z *= scale; v.w *= scale;
    ((float4*)(g_wf + row * Dd))[lane] = v;
}

// ---------------------------------------------------------------------------
// Kernel 2: P[b][t][d] = sum_n wf[b,t,n,d]
// ---------------------------------------------------------------------------
__global__ __launch_bounds__(128) void psum_kernel() {
    int bt = blockIdx.x;
    int d = threadIdx.x;
    const float* base = g_wf + (size_t)bt * Nn * Dd + d;
    float s = 0.0f;
#pragma unroll 4
    for (int n = 0; n < Nn; n++) s += base[n * Dd];
    g_P[bt * Dd + d] = s;
}

// ---------------------------------------------------------------------------
// Kernel 3: one block per (b, tw) window. 256 threads, 8x8 register tiles.
//   dis_j = f(S . wf_j)             (384 dots)
//   M     = wf^T diag(dis) feat     (128x128, K=384)
//   agg   = diag(dis_last) wf_last @ M
//   t1    = relu(agg @ W1 + b1); t2 = t1 @ W2 + b2
//   out   = LN(feat_last + t2) * gamma + beta
// ---------------------------------------------------------------------------
#define SMEM_FLOATS 41472
#define SMEM_BYTES  (SMEM_FLOATS * 4)

__global__ __launch_bounds__(256, 1)
void fused_kernel(const float* __restrict__ feat,
                  const float* __restrict__ W1, const float* __restrict__ b1,
                  const float* __restrict__ W2, const float* __restrict__ b2,
                  const float* __restrict__ gamma, const float* __restrict__ beta,
                  float* __restrict__ out) {
    extern __shared__ float sm[];
    float* tileA = sm;              // 32 x 128  (4096)
    float* tileB = sm + 4096;       // 32 x 128  (4096)
    float* Ms    = sm + 8192;       // 128 x 128 (16384): M, then W1, then W2
    float* Xs    = sm + 24576;      // 128 x 128 (16384): wf_last, agg, t1
    float* dis   = sm + 40960;      // 384
    float* Sv    = sm + 41344;      // 128

    const int tid = threadIdx.x;
    const int bw = blockIdx.x;                  // 0..495
    const int b = bw / TWw, tw = bw % TWw;
    const float* win  = feat + (size_t)(b * Tt + tw) * Nn * Dd;   // 384x128 contiguous
    const float* wwin = g_wf + (size_t)(b * Tt + tw) * Nn * Dd;

    // ---- Stage A: window sum S from precomputed per-timestep sums
    if (tid < Dd) {
        int base = (b * Tt + tw) * Dd + tid;
        Sv[tid] = g_P[base] + g_P[base + Dd] + g_P[base + 2 * Dd];
    }
    __syncthreads();

    // ---- Stage B: dis_j = deg>0 ? rsqrt(max(deg,1e-38)) : 0, deg = S.wf_j
    {
        int warp = tid >> 5, lane = tid & 31;
        float4 s4 = ((const float4*)Sv)[lane];
        for (int j = warp; j < 3 * Nn; j += 8) {
            float4 v = ((const float4*)(wwin + j * Dd))[lane];
            float p = v.x * s4.x + v.y * s4.y + v.z * s4.z + v.w * s4.w;
#pragma unroll
            for (int off = 16; off; off >>= 1) p += __shfl_xor_sync(0xffffffffu, p, off);
            if (lane == 0) dis[j] = (p > 0.0f) ? rsqrtf(fmaxf(p, 1e-38f)) : 0.0f;
        }
    }
    __syncthreads();

    const int ty = tid >> 4, tx = tid & 15;
    const int row0 = ty * 8, col0 = tx * 8;
    float acc[8][8];

    // ---- Stage C: M[d1][d2] = sum_j dis_j * wf[j][d1] * feat[j][d2]  (K=384)
#pragma unroll
    for (int i = 0; i < 8; i++)
#pragma unroll
        for (int j = 0; j < 8; j++) acc[i][j] = 0.0f;

    for (int kc = 0; kc < 12; kc++) {
        for (int i = tid; i < 1024; i += 256) {
            int kl = i >> 5;                            // row within 32-chunk
            float dj = dis[kc * 32 + kl];
            float4 a = ((const float4*)(wwin + kc * 4096))[i];
            a.x *= dj; a.y *= dj; a.z *= dj; a.w *= dj;
            ((float4*)tileA)[i] = a;
            ((float4*)tileB)[i] = ((const float4*)(win + kc * 4096))[i];
        }
        __syncthreads();
#pragma unroll 2
        for (int k = 0; k < 32; k++) {
            float4 a0 = *(const float4*)&tileA[k * 128 + row0];
            float4 a1 = *(const float4*)&tileA[k * 128 + row0 + 4];
            float4 c0 = *(const float4*)&tileB[k * 128 + col0];
            float4 c1 = *(const float4*)&tileB[k * 128 + col0 + 4];
            float ar[8] = {a0.x, a0.y, a0.z, a0.w, a1.x, a1.y, a1.z, a1.w};
            float br[8] = {c0.x, c0.y, c0.z, c0.w, c1.x, c1.y, c1.z, c1.w};
#pragma unroll
            for (int i = 0; i < 8; i++)
#pragma unroll
                for (int j = 0; j < 8; j++) acc[i][j] += ar[i] * br[j];
        }
        __syncthreads();
    }
    // write M, load wf_last into Xs
#pragma unroll
    for (int i = 0; i < 8; i++)
#pragma unroll
        for (int j = 0; j < 8; j++) Ms[(row0 + i) * 128 + col0 + j] = acc[i][j];
    for (int i = tid; i < 4096; i += 256)
        ((float4*)Xs)[i] = ((const float4*)(wwin + 2 * Nn * Dd))[i];
    __syncthreads();

    // ---- Stage D: agg = diag(dis[256..]) * (wf_last @ M)
#pragma unroll
    for (int i = 0; i < 8; i++)
#pragma unroll
        for (int j = 0; j < 8; j++) acc[i][j] = 0.0f;
#pragma unroll 2
    for (int k = 0; k < 128; k++) {
        float4 c0 = *(const float4*)&Ms[k * 128 + col0];
        float4 c1 = *(const float4*)&Ms[k * 128 + col0 + 4];
        float br[8] = {c0.x, c0.y, c0.z, c0.w, c1.x, c1.y, c1.z, c1.w};
        float ar[8];
#pragma unroll
        for (int i = 0; i < 8; i++) ar[i] = Xs[(row0 + i) * 128 + k];
#pragma unroll
        for (int i = 0; i < 8; i++)
#pragma unroll
            for (int j = 0; j < 8; j++) acc[i][j] += ar[i] * br[j];
    }
    {
        float di[8];
#pragma unroll
        for (int i = 0; i < 8; i++) di[i] = dis[2 * Nn + row0 + i];
#pragma unroll
        for (int i = 0; i < 8; i++)
#pragma unroll
            for (int j = 0; j < 8; j++) acc[i][j] *= di[i];
    }
    __syncthreads();
#pragma unroll
    for (int i = 0; i < 8; i++)
#pragma unroll
        for (int j = 0; j < 8; j++) Xs[(row0 + i) * 128 + col0 + j] = acc[i][j];
    for (int i = tid; i < 4096; i += 256)
        ((float4*)Ms)[i] = ((const float4*)W1)[i];
    __syncthreads();

    // ---- Stage E: t1 = relu(agg @ W1 + b1)
#pragma unroll
    for (int i = 0; i < 8; i++)
#pragma unroll
        for (int j = 0; j < 8; j++) acc[i][j] = 0.0f;
#pragma unroll 2
    for (int k = 0; k < 128; k++) {
        float4 c0 = *(const float4*)&Ms[k * 128 + col0];
        float4 c1 = *(const float4*)&Ms[k * 128 + col0 + 4];
        float br[8] = {c0.x, c0.y, c0.z, c0.w, c1.x, c1.y, c1.z, c1.w};
        float ar[8];
#pragma unroll
        for (int i = 0; i < 8; i++) ar[i] = Xs[(row0 + i) * 128 + k];
#pragma unroll
        for (int i = 0; i < 8; i++)
#pragma unroll
            for (int j = 0; j < 8; j++) acc[i][j] += ar[i] * br[j];
    }
    {
        float4 v0 = ((const float4*)b1)[tx * 2];
        float4 v1 = ((const float4*)b1)[tx * 2 + 1];
        float bj[8] = {v0.x, v0.y, v0.z, v0.w, v1.x, v1.y, v1.z, v1.w};
#pragma unroll
        for (int i = 0; i < 8; i++)
#pragma unroll
            for (int j = 0; j < 8; j++) acc[i][j] = fmaxf(acc[i][j] + bj[j], 0.0f);
    }
    __syncthreads();
#pragma unroll
    for (int i = 0; i < 8; i++)
#pragma unroll
        for (int j = 0; j < 8; j++) Xs[(row0 + i) * 128 + col0 + j] = acc[i][j];
    for (int i = tid; i < 4096; i += 256)
        ((float4*)Ms)[i] = ((const float4*)W2)[i];
    __syncthreads();

    // ---- Stage F: t2 = t1 @ W2 + b2; s = feat_last + t2; LayerNorm
#pragma unroll
    for (int i = 0; i < 8; i++)
#pragma unroll
        for (int j = 0; j < 8; j++) acc[i][j] = 0.0f;
#pragma unroll 2
    for (int k = 0; k < 128; k++) {
        float4 c0 = *(const float4*)&Ms[k * 128 + col0];
        float4 c1 = *(const float4*)&Ms[k * 128 + col0 + 4];
        float br[8] = {c0.x, c0.y, c0.z, c0.w, c1.x, c1.y, c1.z, c1.w};
        float ar[8];
#pragma unroll
        for (int i = 0; i < 8; i++) ar[i] = Xs[(row0 + i) * 128 + k];
#pragma unroll
        for (int i = 0; i < 8; i++)
#pragma unroll
            for (int j = 0; j < 8; j++) acc[i][j] += ar[i] * br[j];
    }

    {
        float4 v0 = ((const float4*)b2)[tx * 2];
        float4 v1 = ((const float4*)b2)[tx * 2 + 1];
        float bj[8] = {v0.x, v0.y, v0.z, v0.w, v1.x, v1.y, v1.z, v1.w};
        float4 g0 = ((const float4*)gamma)[tx * 2];
        float4 g1 = ((const float4*)gamma)[tx * 2 + 1];
        float gj[8] = {g0.x, g0.y, g0.z, g0.w, g1.x, g1.y, g1.z, g1.w};
        float4 e0 = ((const float4*)beta)[tx * 2];
        float4 e1 = ((const float4*)beta)[tx * 2 + 1];
        float ej[8] = {e0.x, e0.y, e0.z, e0.w, e1.x, e1.y, e1.z, e1.w};

        const float* fl = win + 2 * Nn * Dd;       // feat[b, tw+2]
        float* outp = out + (size_t)(b * TWw + tw) * Nn * Dd;

#pragma unroll
        for (int i = 0; i < 8; i++) {
            float4 f0 = *(const float4*)&fl[(row0 + i) * 128 + col0];
            float4 f1 = *(const float4*)&fl[(row0 + i) * 128 + col0 + 4];
            float fr[8] = {f0.x, f0.y, f0.z, f0.w, f1.x, f1.y, f1.z, f1.w};
            float s = 0.0f, sq = 0.0f;
#pragma unroll
            for (int j = 0; j < 8; j++) {
                float vv = acc[i][j] + bj[j] + fr[j];
                acc[i][j] = vv;
                s += vv;
                sq += vv * vv;
            }
#pragma unroll
            for (int off = 8; off; off >>= 1) {
                s  += __shfl_xor_sync(0xffffffffu, s, off);
                sq += __shfl_xor_sync(0xffffffffu, sq, off);
            }
            float mu = s * 0.0078125f;                       // /128
            float var = sq * 0.0078125f - mu * mu;
            float rstd = rsqrtf(var + 1e-5f);
            float4 o0, o1;
            o0.x = (acc[i][0] - mu) * rstd * gj[0] + ej[0];
            o0.y = (acc[i][1] - mu) * rstd * gj[1] + ej[1];
            o0.z = (acc[i][2] - mu) * rstd * gj[2] + ej[2];
            o0.w = (acc[i][3] - mu) * rstd * gj[3] + ej[3];
            o1.x = (acc[i][4] - mu) * rstd * gj[4] + ej[4];
            o1.y = (acc[i][5] - mu) * rstd * gj[5] + ej[5];
            o1.z = (acc[i][6] - mu) * rstd * gj[6] + ej[6];
            o1.w = (acc[i][7] - mu) * rstd * gj[7] + ej[7];
            *(float4*)&outp[(row0 + i) * 128 + col0]     = o0;
            *(float4*)&outp[(row0 + i) * 128 + col0 + 4] = o1;
        }
    }
}

// ---------------------------------------------------------------------------
extern "C" void kernel_launch(void* const* d_in, const int* in_sizes, int n_in,
                              void* d_out, int out_size) {
    const float* feat  = (const float*)d_in[0];
    const float* w     = (const float*)d_in[1];
    const float* W1    = (const float*)d_in[2];
    const float* b1    = (const float*)d_in[3];
    const float* W2    = (const float*)d_in[4];
    const float* b2    = (const float*)d_in[5];
    const float* gamma = (const float*)d_in[6];
    const float* beta  = (const float*)d_in[7];
    float* out = (float*)d_out;

    cudaFuncSetAttribute(fused_kernel, cudaFuncAttributeMaxDynamicSharedMemorySize,
                         SMEM_BYTES);

    wf_kernel<<<(Bn * Tt * Nn) / 8, 256>>>(feat, w);
    psum_kernel<<<Bn * Tt, 128>>>();
    fused_kernel<<<Bn * TWw, 256, SMEM_BYTES>>>(feat, W1, b1, W2, b2, gamma, beta, out);
}

// round 4
// speedup vs baseline: 1.0593x; 1.0593x over previous
#include <cuda_runtime.h>
#include <cuda_bf16.h>
#include <cstdint>

#define Bn 8
#define Tt 64
#define TWw 62
#define NBT (Bn*Tt)
#define TILE 16384

// ---------------- device scratch ----------------
__device__ float g_wf [(size_t)NBT*TILE];      // wf fp32 [bt][n][d]
__device__ float g_wfT[(size_t)NBT*TILE];      // wf fp32 [bt][d][n]
__device__ float g_P  [NBT*128];
__device__ unsigned short g_wfh[(size_t)NBT*TILE], g_wfl[(size_t)NBT*TILE]; // wf bf16 [n][d]
__device__ unsigned short g_fTh[(size_t)NBT*TILE], g_fTl[(size_t)NBT*TILE]; // featT bf16 [d][n]
__device__ unsigned short g_W1h[TILE], g_W1l[TILE];   // W1T [h][i]
__device__ unsigned short g_W2h[TILE], g_W2l[TILE];   // W2T [o][i]

// ---------------- helpers ----------------
__device__ __forceinline__ uint32_t smem_u32(const void* p){
    uint32_t a;
    asm("{ .reg .u64 t; cvta.to.shared.u64 t, %1; cvt.u32.u64 %0, t; }" : "=r"(a) : "l"(p));
    return a;
}
__device__ __forceinline__ void ldsm4(uint32_t addr, uint32_t r[4]){
    asm volatile("ldmatrix.sync.aligned.m8n8.x4.shared.b16 {%0,%1,%2,%3}, [%4];"
        : "=r"(r[0]), "=r"(r[1]), "=r"(r[2]), "=r"(r[3]) : "r"(addr));
}
__device__ __forceinline__ void mma16816(float* c, const uint32_t a[4], uint32_t b0, uint32_t b1){
    asm volatile("mma.sync.aligned.m16n8k16.row.col.f32.bf16.bf16.f32 "
        "{%0,%1,%2,%3}, {%4,%5,%6,%7}, {%8,%9}, {%0,%1,%2,%3};"
        : "+f"(c[0]), "+f"(c[1]), "+f"(c[2]), "+f"(c[3])
        : "r"(a[0]), "r"(a[1]), "r"(a[2]), "r"(a[3]), "r"(b0), "r"(b1));
}
__device__ __forceinline__ void split2(float a, float b, uint32_t& hw, uint32_t& lw){
    __nv_bfloat16 ah = __float2bfloat16(a);
    __nv_bfloat16 bh = __float2bfloat16(b);
    __nv_bfloat16 al = __float2bfloat16(a - __bfloat162float(ah));
    __nv_bfloat16 bl = __float2bfloat16(b - __bfloat162float(bh));
    hw = (uint32_t)__bfloat16_as_ushort(ah) | ((uint32_t)__bfloat16_as_ushort(bh) << 16);
    lw = (uint32_t)__bfloat16_as_ushort(al) | ((uint32_t)__bfloat16_as_ushort(bl) << 16);
}

// ===========================================================================
// Precompute per (b,t)
// ===========================================================================
#define PAD 136
#define PREP_SMEM ((2*128*PAD + 128)*4)

__global__ __launch_bounds__(256) void prep_kernel(const float* __restrict__ feat,
                                                   const float* __restrict__ w){
    extern __shared__ float sp[];
    float* ft  = sp;
    float* wt  = sp + 128*PAD;
    float* sig = sp + 2*128*PAD;
    const int tid = threadIdx.x;
    const int bt  = blockIdx.x;
    if (tid < 128) sig[tid] = 1.0f / (1.0f + expf(-w[tid]));

    const float* src = feat + (size_t)bt * TILE;
    for (int i = tid; i < 4096; i += 256){
        int r = i >> 5, c4 = i & 31;
        *(float4*)&ft[r*PAD + c4*4] = ((const float4*)src)[i];
    }
    __syncthreads();

    const int wid = tid >> 5, lane = tid & 31;
    float4 sg = ((const float4*)sig)[lane];
    uint32_t* bh = (uint32_t*)g_wfh;
    uint32_t* bl = (uint32_t*)g_wfl;
#pragma unroll
    for (int k = 0; k < 16; k++){
        int r = wid + 8*k;
        float4 v = *(const float4*)&ft[r*PAD + lane*4];
        v.x *= sg.x; v.y *= sg.y; v.z *= sg.z; v.w *= sg.w;
        float sq = v.x*v.x + v.y*v.y + v.z*v.z + v.w*v.w;
#pragma unroll
        for (int off = 16; off; off >>= 1) sq += __shfl_xor_sync(0xffffffffu, sq, off);
        float sc = 1.0f / fmaxf(sqrtf(sq), 1e-12f);
        v.x *= sc; v.y *= sc; v.z *= sc; v.w *= sc;
        *(float4*)&wt[r*PAD + lane*4] = v;
        ((float4*)(g_wf + (size_t)bt*TILE + (size_t)r*128))[lane] = v;
        uint32_t h0,l0,h1,l1;
        split2(v.x, v.y, h0, l0);
        split2(v.z, v.w, h1, l1);
        size_t base = ((size_t)bt*TILE + (size_t)r*128 + lane*4) >> 1;
        bh[base] = h0;     bl[base] = l0;
        bh[base + 1] = h1; bl[base + 1] = l1;
    }
    __syncthreads();

    if (tid < 128){
        float s = 0.0f;
        for (int n = 0; n < 128; n++) s += wt[n*PAD + tid];
        g_P[bt*128 + tid] = s;
    }
    // wfT fp32 [d][n]
    for (int i = tid; i < 4096; i += 256){
        int d = i >> 5, n4 = (i & 31)*4;
        float4 v;
        v.x = wt[(n4  )*PAD + d];
        v.y = wt[(n4+1)*PAD + d];
        v.z = wt[(n4+2)*PAD + d];
        v.w = wt[(n4+3)*PAD + d];
        ((float4*)(g_wfT + (size_t)bt*TILE))[i] = v;
    }
    // featT bf16 blobs [d][n]
    uint32_t* fh = (uint32_t*)g_fTh;
    uint32_t* fl = (uint32_t*)g_fTl;
    for (int i = tid; i < 8192; i += 256){
        int d = i >> 6, n2 = (i & 63)*2;
        uint32_t h, l;
        split2(ft[n2*PAD + d], ft[(n2+1)*PAD + d], h, l);
        size_t o = ((size_t)bt*TILE + (size_t)d*128 + n2) >> 1;
        fh[o] = h; fl[o] = l;
    }
}

#define W_SMEM (128*PAD*4)
__global__ __launch_bounds__(256) void prepW_kernel(const float* __restrict__ W1,
                                                    const float* __restrict__ W2){
    extern __shared__ float sw[];
    const float* W = blockIdx.x ? W2 : W1;
    uint32_t* bh = (uint32_t*)(blockIdx.x ? g_W2h : g_W1h);
    uint32_t* bl = (uint32_t*)(blockIdx.x ? g_W2l : g_W1l);
    const int tid = threadIdx.x;
    for (int i = tid; i < 4096; i += 256){
        int r = i >> 5, c4 = i & 31;
        *(float4*)&sw[r*PAD + c4*4] = ((const float4*)W)[i];
    }
    __syncthreads();
    for (int i = tid; i < 8192; i += 256){
        int o = i >> 6, in2 = (i & 63)*2;
        uint32_t h, l;
        split2(sw[in2*PAD + o], sw[(in2+1)*PAD + o], h, l);
        bh[(o*128 + in2) >> 1] = h;
        bl[(o*128 + in2) >> 1] = l;
    }
}

// ===========================================================================
// Fused per-window kernel (mma.sync bf16 hi/lo x3)
// ===========================================================================
// smem byte offsets
#define XH_O 0
#define XL_O 34816
#define YH_O 69632
#define YL_O 104448
#define SAH_O 139264
#define SAL_O 149504
#define SBH_O 159744
#define SBL_O 169984
#define DIS_O 180224
#define B1_O  181760
#define B2_O  182272
#define GM_O  182784
#define BT_O  183296
#define SV_O  183808
#define PSS_O 184320
#define PSQ_O 185344
#define FUSED_SMEM 186368

#define LDX 136
#define LDS_ 40

// one k16 step for the whole warp tile (2 m16 x 8 n8), 3-product bf16 emulation
__device__ __forceinline__ void mma_k16(uint32_t sb,
        uint32_t aH, uint32_t aL, int lda, int ka0,
        uint32_t bH, uint32_t bL, int ldb, int kb0,
        float (*acc)[4], int lane, int wr, int wc){
    const int arow = lane & 15, chalf = (lane >> 4) << 3;
    uint32_t Ah[2][4], Al[2][4];
#pragma unroll
    for (int mi = 0; mi < 2; mi++){
        uint32_t off = (uint32_t)((wr*32 + mi*16 + arow) * lda + ka0 + chalf) * 2;
        ldsm4(sb + aH + off, Ah[mi]);
        ldsm4(sb + aL + off, Al[mi]);
    }
#pragma unroll
    for (int ng = 0; ng < 4; ng++){
        uint32_t off = (uint32_t)((wc*64 + ng*16 + arow) * ldb + kb0 + chalf) * 2;
        uint32_t Bh[4], Bl[4];
        ldsm4(sb + bH + off, Bh);
        ldsm4(sb + bL + off, Bl);
#pragma unroll
        for (int mi = 0; mi < 2; mi++){
            float* c0 = acc[mi*8 + ng*2];
            float* c1 = acc[mi*8 + ng*2 + 1];
            mma16816(c0, Ah[mi], Bh[0], Bh[2]);
            mma16816(c0, Ah[mi], Bl[0], Bl[2]);
            mma16816(c0, Al[mi], Bh[0], Bh[2]);
            mma16816(c1, Ah[mi], Bh[1], Bh[3]);
            mma16816(c1, Ah[mi], Bl[1], Bl[3]);
            mma16816(c1, Al[mi], Bh[1], Bh[3]);
        }
    }
}

// copy a 128x32 bf16 hi/lo chunk (chunk c of a [128][128] blob) into stride-40 smem
__device__ __forceinline__ void stage_blob(uint8_t* smb, uint32_t dH, uint32_t dL,
        const unsigned short* __restrict__ srch, const unsigned short* __restrict__ srcl,
        int c, int tid){
    const uint4* sh = (const uint4*)srch;
    const uint4* sl = (const uint4*)srcl;
    uint4* dh = (uint4*)(smb + dH);
    uint4* dl = (uint4*)(smb + dL);
    for (int i = tid; i < 512; i += 256){
        int r = i >> 2, s = i & 3;
        int si = r*16 + c*4 + s;
        int di = r*5 + s;
        dh[di] = sh[si];
        dl[di] = sl[si];
    }
}

// write accum tile to bf16 hi/lo stride-136 smem tile.
// MODE 0: plain; 1: row-scale smf[xo + row]; 2: col-bias smf[xo + col] + relu
template<int MODE>
__device__ __forceinline__ void store_acc(uint8_t* smb, uint32_t oH, uint32_t oL,
        float (*acc)[4], const float* smf, int xo, int lane, int wr, int wc){
    const int g = lane >> 2, t = lane & 3;
#pragma unroll
    for (int mi = 0; mi < 2; mi++){
        int r0 = wr*32 + mi*16 + g;
#pragma unroll
        for (int ni = 0; ni < 8; ni++){
            int col = wc*64 + ni*8 + t*2;
            float* a = acc[mi*8 + ni];
            float v0 = a[0], v1 = a[1], v2 = a[2], v3 = a[3];
            if (MODE == 1){
                float s0 = smf[xo + r0], s1 = smf[xo + r0 + 8];
                v0 *= s0; v1 *= s0; v2 *= s1; v3 *= s1;
            }
            if (MODE == 2){
                float q0 = smf[xo + col], q1 = smf[xo + col + 1];
                v0 = fmaxf(v0 + q0, 0.0f); v1 = fmaxf(v1 + q1, 0.0f);
                v2 = fmaxf(v2 + q0, 0.0f); v3 = fmaxf(v3 + q1, 0.0f);
            }
            uint32_t h0,l0,h1,l1;
            split2(v0, v1, h0, l0);
            split2(v2, v3, h1, l1);
            uint32_t o0 = (uint32_t)(r0*LDX + col)*2, o1 = (uint32_t)((r0+8)*LDX + col)*2;
            *(uint32_t*)(smb + oH + o0) = h0;  *(uint32_t*)(smb + oL + o0) = l0;
            *(uint32_t*)(smb + oH + o1) = h1;  *(uint32_t*)(smb + oL + o1) = l1;
        }
    }
}

__device__ __forceinline__ void zero_acc(float (*acc)[4]){
#pragma unroll
    for (int i = 0; i < 16; i++)
#pragma unroll
        for (int j = 0; j < 4; j++) acc[i][j] = 0.0f;
}

__global__ __launch_bounds__(256)
void fused_kernel(const float* __restrict__ feat,
                  const float* __restrict__ b1, const float* __restrict__ b2,
                  const float* __restrict__ gamma, const float* __restrict__ beta,
                  float* __restrict__ out){
    extern __shared__ uint8_t smb[];
    float* smf = (float*)smb;
    const uint32_t sb = smem_u32(smb);
    const int tid = threadIdx.x, wid = tid >> 5, lane = tid & 31;
    const int wr = wid & 3, wc = wid >> 2;
    const int bw = blockIdx.x, b = bw / TWw, tw = bw % TWw;
    const size_t bt0 = (size_t)(b*Tt + tw);

    if (tid < 128){
        smf[B1_O/4 + tid] = b1[tid];
        smf[B2_O/4 + tid] = b2[tid];
        smf[GM_O/4 + tid] = gamma[tid];
        smf[BT_O/4 + tid] = beta[tid];
        int pb = (int)bt0*128 + tid;
        smf[SV_O/4 + tid] = g_P[pb] + g_P[pb + 128] + g_P[pb + 256];
    }
    __syncthreads();

    // dis_j = deg>0 ? rsqrt(max(deg,1e-38)) : 0
    {
        float4 s4 = ((const float4*)(smf + SV_O/4))[lane];
        const float* wwin = g_wf + bt0 * TILE;
        for (int j = wid; j < 384; j += 8){
            float4 v = ((const float4*)(wwin + (size_t)j*128))[lane];
            float p = v.x*s4.x + v.y*s4.y + v.z*s4.z + v.w*s4.w;
#pragma unroll
            for (int off = 16; off; off >>= 1) p += __shfl_xor_sync(0xffffffffu, p, off);
            if (lane == 0) smf[DIS_O/4 + j] = (p > 0.0f) ? rsqrtf(fmaxf(p, 1e-38f)) : 0.0f;
        }
    }
    __syncthreads();

    float acc[16][4];

    // ---------------- Stage C: Mt[d2][d1], K=384 ----------------
    zero_acc(acc);
    for (int t2 = 0; t2 < 3; t2++){
        const unsigned short* ah = g_fTh + (bt0 + t2)*TILE;
        const unsigned short* al = g_fTl + (bt0 + t2)*TILE;
        const float* wfTp = g_wfT + (bt0 + t2)*TILE;
        for (int c = 0; c < 4; c++){
            __syncthreads();
            stage_blob(smb, SAH_O, SAL_O, ah, al, c, tid);
            // B = wfT * dis (split on the fly)
            for (int i = tid; i < 2048; i += 256){
                int r = i >> 4, kk = (i & 15)*2;
                int j = c*32 + kk;
                float2 v = *(const float2*)(wfTp + r*128 + j);
                float d0 = smf[DIS_O/4 + t2*128 + j];
                float d1 = smf[DIS_O/4 + t2*128 + j + 1];
                uint32_t h, l;
                split2(v.x*d0, v.y*d1, h, l);
                *(uint32_t*)(smb + SBH_O + (uint32_t)(r*LDS_ + kk)*2) = h;
                *(uint32_t*)(smb + SBL_O + (uint32_t)(r*LDS_ + kk)*2) = l;
            }
            __syncthreads();
            mma_k16(sb, SAH_O, SAL_O, LDS_, 0,  SBH_O, SBL_O, LDS_, 0,  acc, lane, wr, wc);
            mma_k16(sb, SAH_O, SAL_O, LDS_, 16, SBH_O, SBL_O, LDS_, 16, acc, lane, wr, wc);
        }
    }
    __syncthreads();
    store_acc<0>(smb, XH_O, XL_O, acc, smf, 0, lane, wr, wc);
    __syncthreads();

    // ---------------- Stage D: agg[node][d2] = wf2 @ M ----------------
    zero_acc(acc);
    {
        const unsigned short* ah = g_wfh + (bt0 + 2)*TILE;
        const unsigned short* al = g_wfl + (bt0 + 2)*TILE;
        for (int c = 0; c < 4; c++){
            __syncthreads();
            stage_blob(smb, SAH_O, SAL_O, ah, al, c, tid);
            __syncthreads();
            mma_k16(sb, SAH_O, SAL_O, LDS_, 0,  XH_O, XL_O, LDX, c*32,      acc, lane, wr, wc);
            mma_k16(sb, SAH_O, SAL_O, LDS_, 16, XH_O, XL_O, LDX, c*32 + 16, acc, lane, wr, wc);
        }
    }
    __syncthreads();
    store_acc<1>(smb, YH_O, YL_O, acc, smf, DIS_O/4 + 256, lane, wr, wc);
    __syncthreads();

    // ---------------- Stage E: t1 = relu(aggS @ W1 + b1) ----------------
    zero_acc(acc);
    for (int c = 0; c < 4; c++){
        __syncthreads();
        stage_blob(smb, SBH_O, SBL_O, g_W1h, g_W1l, c, tid);
        __syncthreads();
        mma_k16(sb, YH_O, YL_O, LDX, c*32,      SBH_O, SBL_O, LDS_, 0,  acc, lane, wr, wc);
        mma_k16(sb, YH_O, YL_O, LDX, c*32 + 16, SBH_O, SBL_O, LDS_, 16, acc, lane, wr, wc);
    }
    __syncthreads();
    store_acc<2>(smb, XH_O, XL_O, acc, smf, B1_O/4, lane, wr, wc);
    __syncthreads();

    // ---------------- Stage F: t2 = t1 @ W2 ----------------
    zero_acc(acc);
    for (int c = 0; c < 4; c++){
        __syncthreads();
        stage_blob(smb, SBH_O, SBL_O, g_W2h, g_W2l, c, tid);
        __syncthreads();
        mma_k16(sb, XH_O, XL_O, LDX, c*32,      SBH_O, SBL_O, LDS_, 0,  acc, lane, wr, wc);
        mma_k16(sb, XH_O, XL_O, LDX, c*32 + 16, SBH_O, SBL_O, LDS_, 16, acc, lane, wr, wc);
    }

    // ---------------- Epilogue: +b2 +feat, LayerNorm, store ----------------
    {
        const int g = lane >> 2, t = lane & 3;
        const float* featLast = feat + (bt0 + 2)*TILE;
#pragma unroll
        for (int mi = 0; mi < 2; mi++){
            int r0 = wr*32 + mi*16 + g;
            float s0 = 0.0f, q0 = 0.0f, s1 = 0.0f, q1 = 0.0f;
#pragma unroll
            for (int ni = 0; ni < 8; ni++){
                int col = wc*64 + ni*8 + t*2;
                float* a = acc[mi*8 + ni];
                float bb0 = smf[B2_O/4 + col], bb1 = smf[B2_O/4 + col + 1];
                float2 f0 = *(const float2*)(featLast + r0*128 + col);
                float2 f1 = *(const float2*)(featLast + (r0+8)*128 + col);
                a[0] += bb0 + f0.x; a[1] += bb1 + f0.y;
                a[2] += bb0 + f1.x; a[3] += bb1 + f1.y;
                s0 += a[0] + a[1];  q0 += a[0]*a[0] + a[1]*a[1];
                s1 += a[2] + a[3];  q1 += a[2]*a[2] + a[3]*a[3];
            }
            s0 += __shfl_xor_sync(0xffffffffu, s0, 1); s0 += __shfl_xor_sync(0xffffffffu, s0, 2);
            q0 += __shfl_xor_sync(0xffffffffu, q0, 1); q0 += __shfl_xor_sync(0xffffffffu, q0, 2);
            s1 += __shfl_xor_sync(0xffffffffu, s1, 1); s1 += __shfl_xor_sync(0xffffffffu, s1, 2);
            q1 += __shfl_xor_sync(0xffffffffu, q1, 1); q1 += __shfl_xor_sync(0xffffffffu, q1, 2);
            if (t == 0){
                smf[PSS_O/4 + r0*2 + wc] = s0;       smf[PSQ_O/4 + r0*2 + wc] = q0;
                smf[PSS_O/4 + (r0+8)*2 + wc] = s1;   smf[PSQ_O/4 + (r0+8)*2 + wc] = q1;
            }
        }
        __syncthreads();
        float* outp = out + (size_t)(b*TWw + tw)*TILE;
#pragma unroll
        for (int mi = 0; mi < 2; mi++){
            int r0 = wr*32 + mi*16 + g;
            float S0 = smf[PSS_O/4 + r0*2] + smf[PSS_O/4 + r0*2 + 1];
            float Q0 = smf[PSQ_O/4 + r0*2] + smf[PSQ_O/4 + r0*2 + 1];
            float S1 = smf[PSS_O/4 + (r0+8)*2] + smf[PSS_O/4 + (r0+8)*2 + 1];
            float Q1 = smf[PSQ_O/4 + (r0+8)*2] + smf[PSQ_O/4 + (r0+8)*2 + 1];
            float mu0 = S0 * 0.0078125f, mu1 = S1 * 0.0078125f;
            float rs0 = rsqrtf(Q0*0.0078125f - mu0*mu0 + 1e-5f);
            float rs1 = rsqrtf(Q1*0.0078125f - mu1*mu1 + 1e-5f);
#pragma unroll
            for (int ni = 0; ni < 8; ni++){
                int col = wc*64 + ni*8 + t*2;
                float* a = acc[mi*8 + ni];
                float gm0 = smf[GM_O/4 + col], gm1 = smf[GM_O/4 + col + 1];
                float bt0v = smf[BT_O/4 + col], bt1v = smf[BT_O/4 + col + 1];
                float2 o0, o1;
                o0.x = (a[0] - mu0)*rs0*gm0 + bt0v;
                o0.y = (a[1] - mu0)*rs0*gm1 + bt1v;
                o1.x = (a[2] - mu1)*rs1*gm0 + bt0v;
                o1.y = (a[3] - mu1)*rs1*gm1 + bt1v;
                *(float2*)(outp + r0*128 + col)     = o0;
                *(float2*)(outp + (r0+8)*128 + col) = o1;
            }
        }
    }
}

// ---------------------------------------------------------------------------
extern "C" void kernel_launch(void* const* d_in, const int* in_sizes, int n_in,
                              void* d_out, int out_size) {
    const float* feat  = (const float*)d_in[0];
    const float* w     = (const float*)d_in[1];
    const float* W1    = (const float*)d_in[2];
    const float* b1    = (const float*)d_in[3];
    const float* W2    = (const float*)d_in[4];
    const float* b2    = (const float*)d_in[5];
    const float* gamma = (const float*)d_in[6];
    const float* beta  = (const float*)d_in[7];
    float* out = (float*)d_out;

    cudaFuncSetAttribute(prep_kernel, cudaFuncAttributeMaxDynamicSharedMemorySize, PREP_SMEM);
    cudaFuncSetAttribute(prepW_kernel, cudaFuncAttributeMaxDynamicSharedMemorySize, W_SMEM);
    cudaFuncSetAttribute(fused_kernel, cudaFuncAttributeMaxDynamicSharedMemorySize, FUSED_SMEM);

    prep_kernel<<<NBT, 256, PREP_SMEM>>>(feat, w);
    prepW_kernel<<<2, 256, W_SMEM>>>(W1, W2);
    fused_kernel<<<Bn*TWw, 256, FUSED_SMEM>>>(feat, b1, b2, gamma, beta, out);
}

// round 5
// speedup vs baseline: 1.4701x; 1.3879x over previous
#include <cuda_runtime.h>
#include <cuda_bf16.h>
#include <cstdint>

#define Bn 8
#define Tt 64
#define TWw 62
#define NBT (Bn*Tt)
#define TILE 16384

// ---------------- device scratch ----------------
__device__ float g_wf [(size_t)NBT*TILE];      // wf fp32 [bt][n][d]
__device__ float g_wfT[(size_t)NBT*TILE];      // wf fp32 [bt][d][n]
__device__ float g_P  [NBT*128];
__device__ unsigned short g_wfh[(size_t)NBT*TILE], g_wfl[(size_t)NBT*TILE]; // wf bf16 [n][d]
__device__ unsigned short g_fTh[(size_t)NBT*TILE], g_fTl[(size_t)NBT*TILE]; // featT bf16 [d][n]
__device__ unsigned short g_W1h[TILE], g_W1l[TILE];   // W1T [h][i]
__device__ unsigned short g_W2h[TILE], g_W2l[TILE];   // W2T [o][i]

// ---------------- helpers ----------------
__device__ __forceinline__ uint32_t smem_u32(const void* p){
    uint32_t a;
    asm("{ .reg .u64 t; cvta.to.shared.u64 t, %1; cvt.u32.u64 %0, t; }" : "=r"(a) : "l"(p));
    return a;
}
__device__ __forceinline__ void ldsm4(uint32_t addr, uint32_t r[4]){
    asm volatile("ldmatrix.sync.aligned.m8n8.x4.shared.b16 {%0,%1,%2,%3}, [%4];"
        : "=r"(r[0]), "=r"(r[1]), "=r"(r[2]), "=r"(r[3]) : "r"(addr));
}
__device__ __forceinline__ void mma16816(float* c, const uint32_t a[4], uint32_t b0, uint32_t b1){
    asm volatile("mma.sync.aligned.m16n8k16.row.col.f32.bf16.bf16.f32 "
        "{%0,%1,%2,%3}, {%4,%5,%6,%7}, {%8,%9}, {%0,%1,%2,%3};"
        : "+f"(c[0]), "+f"(c[1]), "+f"(c[2]), "+f"(c[3])
        : "r"(a[0]), "r"(a[1]), "r"(a[2]), "r"(a[3]), "r"(b0), "r"(b1));
}
__device__ __forceinline__ void split2(float a, float b, uint32_t& hw, uint32_t& lw){
    __nv_bfloat16 ah = __float2bfloat16(a);
    __nv_bfloat16 bh = __float2bfloat16(b);
    __nv_bfloat16 al = __float2bfloat16(a - __bfloat162float(ah));
    __nv_bfloat16 bl = __float2bfloat16(b - __bfloat162float(bh));
    hw = (uint32_t)__bfloat16_as_ushort(ah) | ((uint32_t)__bfloat16_as_ushort(bh) << 16);
    lw = (uint32_t)__bfloat16_as_ushort(al) | ((uint32_t)__bfloat16_as_ushort(bl) << 16);
}
#define CP_COMMIT() asm volatile("cp.async.commit_group;" ::: "memory")
#define CP_WAIT0()  asm volatile("cp.async.wait_group 0;" ::: "memory")

// ===========================================================================
// Kernel 1: wf rows (streaming, high occupancy) + bf16 hi/lo blob
// ===========================================================================
__global__ __launch_bounds__(256) void wf_kernel(const float* __restrict__ feat,
                                                 const float* __restrict__ w){
    __shared__ float sigw[128];
    int tid = threadIdx.x;
    if (tid < 128) sigw[tid] = 1.0f / (1.0f + expf(-w[tid]));
    __syncthreads();
    int warp = tid >> 5, lane = tid & 31;
    size_t row = (size_t)blockIdx.x * 8 + warp;
    float4 v = ((const float4*)(feat + row * 128))[lane];
    float4 sw = ((const float4*)sigw)[lane];
    v.x *= sw.x; v.y *= sw.y; v.z *= sw.z; v.w *= sw.w;
    float sq = v.x*v.x + v.y*v.y + v.z*v.z + v.w*v.w;
#pragma unroll
    for (int off = 16; off; off >>= 1) sq += __shfl_xor_sync(0xffffffffu, sq, off);
    float sc = 1.0f / fmaxf(sqrtf(sq), 1e-12f);
    v.x *= sc; v.y *= sc; v.z *= sc; v.w *= sc;
    ((float4*)(g_wf + row * 128))[lane] = v;
    uint32_t h0,l0,h1,l1;
    split2(v.x, v.y, h0, l0);
    split2(v.z, v.w, h1, l1);
    size_t bi = row*64 + lane*2;
    ((uint32_t*)g_wfh)[bi]   = h0;  ((uint32_t*)g_wfl)[bi]   = l0;
    ((uint32_t*)g_wfh)[bi+1] = h1;  ((uint32_t*)g_wfl)[bi+1] = l1;
}

// ===========================================================================
// Kernel 2: transposes (featT blobs, wfT fp32, W blobs) + P sums
//   grid = NBT*4 (bt x 32-col chunk)  +  8 (W1/W2 x 4 chunks)
// ===========================================================================
__global__ __launch_bounds__(256) void trans_kernel(const float* __restrict__ feat,
                                                    const float* __restrict__ W1,
                                                    const float* __restrict__ W2){
    __shared__ float ft[128*33];
    __shared__ float wt[128*33];
    __shared__ float pp[8*32];
    const int tid = threadIdx.x, blk = blockIdx.x;
    const bool isBT = blk < NBT*4;
    int bt = 0, dc;
    const float *S0, *S1 = nullptr;
    unsigned short *oh, *ol;
    if (isBT){
        bt = blk >> 2; dc = blk & 3;
        S0 = feat + (size_t)bt*TILE;
        S1 = g_wf + (size_t)bt*TILE;
        oh = g_fTh + (size_t)bt*TILE;
        ol = g_fTl + (size_t)bt*TILE;
    } else {
        int k = blk - NBT*4;
        int which = k >> 2; dc = k & 3;
        S0 = which ? W2 : W1;
        oh = which ? g_W2h : g_W1h;
        ol = which ? g_W2l : g_W1l;
    }
    for (int i = tid; i < 1024; i += 256){
        int r = i >> 3, s = i & 7;
        float4 v = *(const float4*)(S0 + (size_t)r*128 + dc*32 + s*4);
        ft[r*33 + s*4    ] = v.x; ft[r*33 + s*4 + 1] = v.y;
        ft[r*33 + s*4 + 2] = v.z; ft[r*33 + s*4 + 3] = v.w;
        if (isBT){
            float4 u = *(const float4*)(S1 + (size_t)r*128 + dc*32 + s*4);
            wt[r*33 + s*4    ] = u.x; wt[r*33 + s*4 + 1] = u.y;
            wt[r*33 + s*4 + 2] = u.z; wt[r*33 + s*4 + 3] = u.w;
        }
    }
    __syncthreads();
    if (isBT){
        int part = tid >> 5, d = tid & 31;
        float s = 0.0f;
        for (int n = part*16; n < part*16 + 16; n++) s += wt[n*33 + d];
        pp[part*32 + d] = s;
    }
    for (int i = tid; i < 2048; i += 256){
        int d = i >> 6, q = i & 63, n0 = q*2;
        uint32_t h, l;
        split2(ft[n0*33 + d], ft[(n0+1)*33 + d], h, l);
        size_t bi = (size_t)(dc*32 + d)*64 + q;
        ((uint32_t*)oh)[bi] = h;
        ((uint32_t*)ol)[bi] = l;
        if (isBT){
            float2 v2 = make_float2(wt[n0*33 + d], wt[(n0+1)*33 + d]);
            *(float2*)(g_wfT + (size_t)bt*TILE + (size_t)(dc*32 + d)*128 + n0) = v2;
        }
    }
    __syncthreads();
    if (isBT && tid < 32){
        float s = 0.0f;
#pragma unroll
        for (int p = 0; p < 8; p++) s += pp[p*32 + tid];
        g_P[bt*128 + dc*32 + tid] = s;
    }
}

// ===========================================================================
// Fused per-window kernel
// ===========================================================================
#define XH_O 0
#define XL_O 34816
#define SAH_O 69632
#define SAL_O 88064
#define SBH_O 106496
#define SBL_O 124928
#define DIS_O 143360
#define B1_O  144896
#define B2_O  145408
#define GM_O  145920
#define BT_O  146432
#define SV_O  146944
#define PSS_O 147456
#define PSQ_O 148480
#define FUSED_SMEM 149504

#define LDX 136
#define LDS_ 72

// one k16 step for warp tile (2 m16 x 8 n8), 3-product bf16 emulation
__device__ __forceinline__ void mma_k16(uint32_t sb,
        uint32_t aH, uint32_t aL, int lda, int ka0,
        uint32_t bH, uint32_t bL, int ldb, int kb0,
        float (*acc)[4], int lane, int wr, int wc){
    const int arow = lane & 15, chalf = (lane >> 4) << 3;
    uint32_t Ah[2][4], Al[2][4];
#pragma unroll
    for (int mi = 0; mi < 2; mi++){
        uint32_t off = (uint32_t)((wr*32 + mi*16 + arow) * lda + ka0 + chalf) * 2;
        ldsm4(sb + aH + off, Ah[mi]);
        ldsm4(sb + aL + off, Al[mi]);
    }
#pragma unroll
    for (int ng = 0; ng < 4; ng++){
        uint32_t off = (uint32_t)((wc*64 + ng*16 + arow) * ldb + kb0 + chalf) * 2;
        uint32_t Bh[4], Bl[4];
        ldsm4(sb + bH + off, Bh);
        ldsm4(sb + bL + off, Bl);
#pragma unroll
        for (int mi = 0; mi < 2; mi++){
            float* c0 = acc[mi*8 + ng*2];
            float* c1 = acc[mi*8 + ng*2 + 1];
            mma16816(c0, Ah[mi], Bh[0], Bh[2]);
            mma16816(c0, Ah[mi], Bl[0], Bl[2]);
            mma16816(c0, Al[mi], Bh[0], Bh[2]);
            mma16816(c1, Ah[mi], Bh[1], Bh[3]);
            mma16816(c1, Ah[mi], Bl[1], Bl[3]);
            mma16816(c1, Al[mi], Bh[1], Bh[3]);
        }
    }
}

// cp.async 64-col chunk c of a [128][128] bf16 blob pair into LDS_-stride smem
__device__ __forceinline__ void stage_cp(uint32_t sb, uint32_t dH, uint32_t dL,
        const unsigned short* __restrict__ sh, const unsigned short* __restrict__ sl,
        int c, int tid){
    const char* gh = (const char*)sh + c*128;
    const char* gl = (const char*)sl + c*128;
    for (int i = tid; i < 2048; i += 256){
        int half = i >> 10, j = i & 1023, r = j >> 3, s = j & 7;
        uint32_t dst = sb + (half ? dL : dH) + (uint32_t)r*144 + s*16;
        const char* src = (half ? gl : gh) + (size_t)r*256 + s*16;
        asm volatile("cp.async.ca.shared.global [%0], [%1], 16;" :: "r"(dst), "l"(src));
    }
}

// write accum tile into X (bf16 hi/lo, stride LDX)
// MODE 0: plain; 1: row-scale smf[xo+row]; 2: col-bias smf[xo+col] + relu
template<int MODE>
__device__ __forceinline__ void store_acc(uint8_t* smb, float (*acc)[4],
        const float* smf, int xo, int lane, int wr, int wc){
    const int g = lane >> 2, t = lane & 3;
#pragma unroll
    for (int mi = 0; mi < 2; mi++){
        int r0 = wr*32 + mi*16 + g;
#pragma unroll
        for (int ni = 0; ni < 8; ni++){
            int col = wc*64 + ni*8 + t*2;
            float* a = acc[mi*8 + ni];
            float v0 = a[0], v1 = a[1], v2 = a[2], v3 = a[3];
            if (MODE == 1){
                float s0 = smf[xo + r0], s1 = smf[xo + r0 + 8];
                v0 *= s0; v1 *= s0; v2 *= s1; v3 *= s1;
            }
            if (MODE == 2){
                float q0 = smf[xo + col], q1 = smf[xo + col + 1];
                v0 = fmaxf(v0 + q0, 0.0f); v1 = fmaxf(v1 + q1, 0.0f);
                v2 = fmaxf(v2 + q0, 0.0f); v3 = fmaxf(v3 + q1, 0.0f);
            }
            uint32_t h0,l0,h1,l1;
            split2(v0, v1, h0, l0);
            split2(v2, v3, h1, l1);
            uint32_t o0 = (uint32_t)(r0*LDX + col)*2, o1 = (uint32_t)((r0+8)*LDX + col)*2;
            *(uint32_t*)(smb + XH_O + o0) = h0;  *(uint32_t*)(smb + XL_O + o0) = l0;
            *(uint32_t*)(smb + XH_O + o1) = h1;  *(uint32_t*)(smb + XL_O + o1) = l1;
        }
    }
}

__device__ __forceinline__ void zero_acc(float (*acc)[4]){
#pragma unroll
    for (int i = 0; i < 16; i++)
#pragma unroll
        for (int j = 0; j < 4; j++) acc[i][j] = 0.0f;
}

__global__ __launch_bounds__(256)
void fused_kernel(const float* __restrict__ feat,
                  const float* __restrict__ b1, const float* __restrict__ b2,
                  const float* __restrict__ gamma, const float* __restrict__ beta,
                  float* __restrict__ out){
    extern __shared__ uint8_t smb[];
    float* smf = (float*)smb;
    const uint32_t sb = smem_u32(smb);
    const int tid = threadIdx.x, wid = tid >> 5, lane = tid & 31;
    const int wr = wid & 3, wc = wid >> 2;
    const int bw = blockIdx.x, b = bw / TWw, tw = bw % TWw;
    const size_t bt0 = (size_t)(b*Tt + tw);

    if (tid < 128){
        smf[B1_O/4 + tid] = b1[tid];
        smf[B2_O/4 + tid] = b2[tid];
        smf[GM_O/4 + tid] = gamma[tid];
        smf[BT_O/4 + tid] = beta[tid];
        int pb = (int)bt0*128 + tid;
        smf[SV_O/4 + tid] = g_P[pb] + g_P[pb + 128] + g_P[pb + 256];
    }
    __syncthreads();

    // dis_j = deg>0 ? rsqrt(max(deg,1e-38)) : 0
    {
        float4 s4 = ((const float4*)(smf + SV_O/4))[lane];
        const float* wwin = g_wf + bt0 * TILE;
        for (int j = wid; j < 384; j += 8){
            float4 v = ((const float4*)(wwin + (size_t)j*128))[lane];
            float p = v.x*s4.x + v.y*s4.y + v.z*s4.z + v.w*s4.w;
#pragma unroll
            for (int off = 16; off; off >>= 1) p += __shfl_xor_sync(0xffffffffu, p, off);
            if (lane == 0) smf[DIS_O/4 + j] = (p > 0.0f) ? rsqrtf(fmaxf(p, 1e-38f)) : 0.0f;
        }
    }
    __syncthreads();

    float acc[16][4];

    // ---------------- Stage C: Mt[d2][d1], K = 3 x 128 ----------------
    zero_acc(acc);
    for (int t2 = 0; t2 < 3; t2++){
        const unsigned short* ah = g_fTh + (bt0 + t2)*TILE;
        const unsigned short* al = g_fTl + (bt0 + t2)*TILE;
        const float* wfTp = g_wfT + (bt0 + t2)*TILE;
        for (int c = 0; c < 2; c++){
            __syncthreads();
            stage_cp(sb, SAH_O, SAL_O, ah, al, c, tid);
            CP_COMMIT();
            // B = wfT * dis, split on the fly (overlaps cp.async)
            for (int i = tid; i < 4096; i += 256){
                int r = i >> 5, q = i & 31;
                int jl = c*64 + q*2;
                float2 v = *(const float2*)(wfTp + (size_t)r*128 + jl);
                float d0 = smf[DIS_O/4 + t2*128 + jl];
                float d1 = smf[DIS_O/4 + t2*128 + jl + 1];
                uint32_t h, l;
                split2(v.x*d0, v.y*d1, h, l);
                uint32_t o = (uint32_t)r*144 + q*4;
                *(uint32_t*)(smb + SBH_O + o) = h;
                *(uint32_t*)(smb + SBL_O + o) = l;
            }
            CP_WAIT0();
            __syncthreads();
#pragma unroll
            for (int k = 0; k < 4; k++)
                mma_k16(sb, SAH_O, SAL_O, LDS_, k*16, SBH_O, SBL_O, LDS_, k*16, acc, lane, wr, wc);
        }
    }
    __syncthreads();
    store_acc<0>(smb, acc, smf, 0, lane, wr, wc);
    __syncthreads();

    // ---------------- Stage D: agg[n][d2] = wf2 @ Mt^T ----------------
    zero_acc(acc);
    {
        const unsigned short* ah = g_wfh + (bt0 + 2)*TILE;
        const unsigned short* al = g_wfl + (bt0 + 2)*TILE;
        for (int c = 0; c < 2; c++){
            if (c) __syncthreads();
            stage_cp(sb, SAH_O, SAL_O, ah, al, c, tid);
            CP_COMMIT(); CP_WAIT0();
            __syncthreads();
#pragma unroll
            for (int k = 0; k < 4; k++)
                mma_k16(sb, SAH_O, SAL_O, LDS_, k*16, XH_O, XL_O, LDX, c*64 + k*16, acc, lane, wr, wc);
        }
    }
    __syncthreads();
    store_acc<1>(smb, acc, smf, DIS_O/4 + 256, lane, wr, wc);
    __syncthreads();

    // ---------------- Stage E: t1 = relu(aggS @ W1 + b1) ----------------
    zero_acc(acc);
    for (int c = 0; c < 2; c++){
        if (c) __syncthreads();
        stage_cp(sb, SBH_O, SBL_O, g_W1h, g_W1l, c, tid);
        CP_COMMIT(); CP_WAIT0();
        __syncthreads();
#pragma unroll
        for (int k = 0; k < 4; k++)
            mma_k16(sb, XH_O, XL_O, LDX, c*64 + k*16, SBH_O, SBL_O, LDS_, k*16, acc, lane, wr, wc);
    }
    __syncthreads();
    store_acc<2>(smb, acc, smf, B1_O/4, lane, wr, wc);
    __syncthreads();

    // ---------------- Stage F: t2 = t1 @ W2 ----------------
    zero_acc(acc);
    for (int c = 0; c < 2; c++){
        if (c) __syncthreads();
        stage_cp(sb, SBH_O, SBL_O, g_W2h, g_W2l, c, tid);
        CP_COMMIT(); CP_WAIT0();
        __syncthreads();
#pragma unroll
        for (int k = 0; k < 4; k++)
            mma_k16(sb, XH_O, XL_O, LDX, c*64 + k*16, SBH_O, SBL_O, LDS_, k*16, acc, lane, wr, wc);
    }

    // ---------------- Epilogue: +b2 +feat, LayerNorm, store ----------------
    {
        const int g = lane >> 2, t = lane & 3;
        const float* featLast = feat + (bt0 + 2)*TILE;
#pragma unroll
        for (int mi = 0; mi < 2; mi++){
            int r0 = wr*32 + mi*16 + g;
            float s0 = 0.0f, q0 = 0.0f, s1 = 0.0f, q1 = 0.0f;
#pragma unroll
            for (int ni = 0; ni < 8; ni++){
                int col = wc*64 + ni*8 + t*2;
                float* a = acc[mi*8 + ni];
                float bb0 = smf[B2_O/4 + col], bb1 = smf[B2_O/4 + col + 1];
                float2 f0 = *(const float2*)(featLast + r0*128 + col);
                float2 f1 = *(const float2*)(featLast + (r0+8)*128 + col);
                a[0] += bb0 + f0.x; a[1] += bb1 + f0.y;
                a[2] += bb0 + f1.x; a[3] += bb1 + f1.y;
                s0 += a[0] + a[1];  q0 += a[0]*a[0] + a[1]*a[1];
                s1 += a[2] + a[3];  q1 += a[2]*a[2] + a[3]*a[3];
            }
            s0 += __shfl_xor_sync(0xffffffffu, s0, 1); s0 += __shfl_xor_sync(0xffffffffu, s0, 2);
            q0 += __shfl_xor_sync(0xffffffffu, q0, 1); q0 += __shfl_xor_sync(0xffffffffu, q0, 2);
            s1 += __shfl_xor_sync(0xffffffffu, s1, 1); s1 += __shfl_xor_sync(0xffffffffu, s1, 2);
            q1 += __shfl_xor_sync(0xffffffffu, q1, 1); q1 += __shfl_xor_sync(0xffffffffu, q1, 2);
            if (t == 0){
                smf[PSS_O/4 + r0*2 + wc] = s0;       smf[PSQ_O/4 + r0*2 + wc] = q0;
                smf[PSS_O/4 + (r0+8)*2 + wc] = s1;   smf[PSQ_O/4 + (r0+8)*2 + wc] = q1;
            }
        }
        __syncthreads();
        float* outp = out + (size_t)(b*TWw + tw)*TILE;
#pragma unroll
        for (int mi = 0; mi < 2; mi++){
            int r0 = wr*32 + mi*16 + g;
            float S0 = smf[PSS_O/4 + r0*2] + smf[PSS_O/4 + r0*2 + 1];
            float Q0 = smf[PSQ_O/4 + r0*2] + smf[PSQ_O/4 + r0*2 + 1];
            float S1 = smf[PSS_O/4 + (r0+8)*2] + smf[PSS_O/4 + (r0+8)*2 + 1];
            float Q1 = smf[PSQ_O/4 + (r0+8)*2] + smf[PSQ_O/4 + (r0+8)*2 + 1];
            float mu0 = S0 * 0.0078125f, mu1 = S1 * 0.0078125f;
            float rs0 = rsqrtf(Q0*0.0078125f - mu0*mu0 + 1e-5f);
            float rs1 = rsqrtf(Q1*0.0078125f - mu1*mu1 + 1e-5f);
#pragma unroll
            for (int ni = 0; ni < 8; ni++){
                int col = wc*64 + ni*8 + t*2;
                float* a = acc[mi*8 + ni];
                float gm0 = smf[GM_O/4 + col], gm1 = smf[GM_O/4 + col + 1];
                float bt0v = smf[BT_O/4 + col], bt1v = smf[BT_O/4 + col + 1];
                float2 o0, o1;
                o0.x = (a[0] - mu0)*rs0*gm0 + bt0v;
                o0.y = (a[1] - mu0)*rs0*gm1 + bt1v;
                o1.x = (a[2] - mu1)*rs1*gm0 + bt0v;
                o1.y = (a[3] - mu1)*rs1*gm1 + bt1v;
                *(float2*)(outp + r0*128 + col)     = o0;
                *(float2*)(outp + (r0+8)*128 + col) = o1;
            }
        }
    }
}

// ---------------------------------------------------------------------------
extern "C" void kernel_launch(void* const* d_in, const int* in_sizes, int n_in,
                              void* d_out, int out_size) {
    const float* feat  = (const float*)d_in[0];
    const float* w     = (const float*)d_in[1];
    const float* W1    = (const float*)d_in[2];
    const float* b1    = (const float*)d_in[3];
    const float* W2    = (const float*)d_in[4];
    const float* b2    = (const float*)d_in[5];
    const float* gamma = (const float*)d_in[6];
    const float* beta  = (const float*)d_in[7];
    float* out = (float*)d_out;

    cudaFuncSetAttribute(fused_kernel, cudaFuncAttributeMaxDynamicSharedMemorySize,
                         FUSED_SMEM);

    wf_kernel<<<NBT*16, 256>>>(feat, w);
    trans_kernel<<<NBT*4 + 8, 256>>>(feat, W1, W2);
    fused_kernel<<<Bn*TWw, 256, FUSED_SMEM>>>(feat, b1, b2, gamma, beta, out);
}

// round 6
// speedup vs baseline: 1.8471x; 1.2564x over previous
#include <cuda_runtime.h>
#include <cuda_bf16.h>
#include <cstdint>

#define Bn 8
#define Tt 64
#define TWw 62
#define NBT (Bn*Tt)
#define TILE 16384

// ---------------- device scratch ----------------
__device__ float g_wf [(size_t)NBT*TILE];      // wf fp32 [bt][n][d]
__device__ float g_wfT[(size_t)NBT*TILE];      // wf fp32 [bt][d][n]
__device__ float g_P  [NBT*128];
__device__ unsigned short g_wfh[(size_t)NBT*TILE], g_wfl[(size_t)NBT*TILE]; // wf bf16 [n][d]
__device__ unsigned short g_fTh[(size_t)NBT*TILE], g_fTl[(size_t)NBT*TILE]; // featT bf16 [d][n]
__device__ unsigned short g_W1h[TILE], g_W1l[TILE];   // W1T [h][i]
__device__ unsigned short g_W2h[TILE], g_W2l[TILE];   // W2T [o][i]

// ---------------- helpers ----------------
__device__ __forceinline__ uint32_t smem_u32(const void* p){
    uint32_t a;
    asm("{ .reg .u64 t; cvta.to.shared.u64 t, %1; cvt.u32.u64 %0, t; }" : "=r"(a) : "l"(p));
    return a;
}
__device__ __forceinline__ void ldsm4(uint32_t addr, uint32_t r[4]){
    asm volatile("ldmatrix.sync.aligned.m8n8.x4.shared.b16 {%0,%1,%2,%3}, [%4];"
        : "=r"(r[0]), "=r"(r[1]), "=r"(r[2]), "=r"(r[3]) : "r"(addr));
}
__device__ __forceinline__ void mma16816(float* c, const uint32_t a[4], uint32_t b0, uint32_t b1){
    asm volatile("mma.sync.aligned.m16n8k16.row.col.f32.bf16.bf16.f32 "
        "{%0,%1,%2,%3}, {%4,%5,%6,%7}, {%8,%9}, {%0,%1,%2,%3};"
        : "+f"(c[0]), "+f"(c[1]), "+f"(c[2]), "+f"(c[3])
        : "r"(a[0]), "r"(a[1]), "r"(a[2]), "r"(a[3]), "r"(b0), "r"(b1));
}
__device__ __forceinline__ void split2(float a, float b, uint32_t& hw, uint32_t& lw){
    __nv_bfloat16 ah = __float2bfloat16(a);
    __nv_bfloat16 bh = __float2bfloat16(b);
    __nv_bfloat16 al = __float2bfloat16(a - __bfloat162float(ah));
    __nv_bfloat16 bl = __float2bfloat16(b - __bfloat162float(bh));
    hw = (uint32_t)__bfloat16_as_ushort(ah) | ((uint32_t)__bfloat16_as_ushort(bh) << 16);
    lw = (uint32_t)__bfloat16_as_ushort(al) | ((uint32_t)__bfloat16_as_ushort(bl) << 16);
}
#define CP_COMMIT() asm volatile("cp.async.commit_group;" ::: "memory")
#define CP_WAIT0()  asm volatile("cp.async.wait_group 0;" ::: "memory")

// ===========================================================================
// Kernel 1: wf rows + bf16 hi/lo blob
// ===========================================================================
__global__ __launch_bounds__(256) void wf_kernel(const float* __restrict__ feat,
                                                 const float* __restrict__ w){
    __shared__ float sigw[128];
    int tid = threadIdx.x;
    if (tid < 128) sigw[tid] = 1.0f / (1.0f + expf(-w[tid]));
    __syncthreads();
    int warp = tid >> 5, lane = tid & 31;
    size_t row = (size_t)blockIdx.x * 8 + warp;
    float4 v = ((const float4*)(feat + row * 128))[lane];
    float4 sw = ((const float4*)sigw)[lane];
    v.x *= sw.x; v.y *= sw.y; v.z *= sw.z; v.w *= sw.w;
    float sq = v.x*v.x + v.y*v.y + v.z*v.z + v.w*v.w;
#pragma unroll
    for (int off = 16; off; off >>= 1) sq += __shfl_xor_sync(0xffffffffu, sq, off);
    float sc = 1.0f / fmaxf(sqrtf(sq), 1e-12f);
    v.x *= sc; v.y *= sc; v.z *= sc; v.w *= sc;
    ((float4*)(g_wf + row * 128))[lane] = v;
    uint32_t h0,l0,h1,l1;
    split2(v.x, v.y, h0, l0);
    split2(v.z, v.w, h1, l1);
    size_t bi = row*64 + lane*2;
    ((uint32_t*)g_wfh)[bi]   = h0;  ((uint32_t*)g_wfl)[bi]   = l0;
    ((uint32_t*)g_wfh)[bi+1] = h1;  ((uint32_t*)g_wfl)[bi+1] = l1;
}

// ===========================================================================
// Kernel 2: transposes + P sums
// ===========================================================================
__global__ __launch_bounds__(256) void trans_kernel(const float* __restrict__ feat,
                                                    const float* __restrict__ W1,
                                                    const float* __restrict__ W2){
    __shared__ float ft[128*33];
    __shared__ float wt[128*33];
    __shared__ float pp[8*32];
    const int tid = threadIdx.x, blk = blockIdx.x;
    const bool isBT = blk < NBT*4;
    int bt = 0, dc;
    const float *S0, *S1 = nullptr;
    unsigned short *oh, *ol;
    if (isBT){
        bt = blk >> 2; dc = blk & 3;
        S0 = feat + (size_t)bt*TILE;
        S1 = g_wf + (size_t)bt*TILE;
        oh = g_fTh + (size_t)bt*TILE;
        ol = g_fTl + (size_t)bt*TILE;
    } else {
        int k = blk - NBT*4;
        int which = k >> 2; dc = k & 3;
        S0 = which ? W2 : W1;
        oh = which ? g_W2h : g_W1h;
        ol = which ? g_W2l : g_W1l;
    }
    for (int i = tid; i < 1024; i += 256){
        int r = i >> 3, s = i & 7;
        float4 v = *(const float4*)(S0 + (size_t)r*128 + dc*32 + s*4);
        ft[r*33 + s*4    ] = v.x; ft[r*33 + s*4 + 1] = v.y;
        ft[r*33 + s*4 + 2] = v.z; ft[r*33 + s*4 + 3] = v.w;
        if (isBT){
            float4 u = *(const float4*)(S1 + (size_t)r*128 + dc*32 + s*4);
            wt[r*33 + s*4    ] = u.x; wt[r*33 + s*4 + 1] = u.y;
            wt[r*33 + s*4 + 2] = u.z; wt[r*33 + s*4 + 3] = u.w;
        }
    }
    __syncthreads();
    if (isBT){
        int part = tid >> 5, d = tid & 31;
        float s = 0.0f;
        for (int n = part*16; n < part*16 + 16; n++) s += wt[n*33 + d];
        pp[part*32 + d] = s;
    }
    for (int i = tid; i < 2048; i += 256){
        int d = i >> 6, q = i & 63, n0 = q*2;
        uint32_t h, l;
        split2(ft[n0*33 + d], ft[(n0+1)*33 + d], h, l);
        size_t bi = (size_t)(dc*32 + d)*64 + q;
        ((uint32_t*)oh)[bi] = h;
        ((uint32_t*)ol)[bi] = l;
        if (isBT){
            float2 v2 = make_float2(wt[n0*33 + d], wt[(n0+1)*33 + d]);
            *(float2*)(g_wfT + (size_t)bt*TILE + (size_t)(dc*32 + d)*128 + n0) = v2;
        }
    }
    __syncthreads();
    if (isBT && tid < 32){
        float s = 0.0f;
#pragma unroll
        for (int p = 0; p < 8; p++) s += pp[p*32 + tid];
        g_P[bt*128 + dc*32 + tid] = s;
    }
}

// ===========================================================================
// Fused per-window kernel: 512 threads, 6 big rounds
// ===========================================================================
#define STGH_O 0
#define STGL_O 34816
#define XH_O   69632
#define XL_O   104448
#define DIS_O  139264
#define B1_O   140800
#define B2_O   141312
#define GM_O   141824
#define BT_O   142336
#define SV_O   142848
#define PSS_O  143360
#define PSQ_O  145408
#define FUSED_SMEM 147456

#define LDX 136

// one k16 step for warp tile 32x32 (2 m16 x 2 n16-groups), 3-product bf16 emu
__device__ __forceinline__ void mma_k16(uint32_t sb,
        uint32_t aH, uint32_t aL, int ka0,
        uint32_t bH, uint32_t bL, int kb0,
        float (*acc)[4], int lane, int wr, int wc){
    const int arow = lane & 15, chalf = (lane >> 4) << 3;
    uint32_t Ah[2][4], Al[2][4];
#pragma unroll
    for (int mi = 0; mi < 2; mi++){
        uint32_t off = (uint32_t)((wr*32 + mi*16 + arow) * LDX + ka0 + chalf) * 2;
        ldsm4(sb + aH + off, Ah[mi]);
        ldsm4(sb + aL + off, Al[mi]);
    }
#pragma unroll
    for (int ng = 0; ng < 2; ng++){
        uint32_t off = (uint32_t)((wc*32 + ng*16 + arow) * LDX + kb0 + chalf) * 2;
        uint32_t Bh[4], Bl[4];
        ldsm4(sb + bH + off, Bh);
        ldsm4(sb + bL + off, Bl);
#pragma unroll
        for (int mi = 0; mi < 2; mi++){
            float* c0 = acc[mi*4 + ng*2];
            float* c1 = acc[mi*4 + ng*2 + 1];
            mma16816(c0, Ah[mi], Bh[0], Bh[2]);
            mma16816(c0, Ah[mi], Bl[0], Bl[2]);
            mma16816(c0, Al[mi], Bh[0], Bh[2]);
            mma16816(c1, Ah[mi], Bh[1], Bh[3]);
            mma16816(c1, Ah[mi], Bl[1], Bl[3]);
            mma16816(c1, Al[mi], Bh[1], Bh[3]);
        }
    }
}

// cp.async a full [128][128] bf16 blob pair into the stage region (stride LDX)
__device__ __forceinline__ void stage_full(uint32_t sb,
        const unsigned short* __restrict__ sh, const unsigned short* __restrict__ sl,
        int tid){
    const char* gh = (const char*)sh;
    const char* gl = (const char*)sl;
    for (int i = tid; i < 4096; i += 512){
        int half = i >> 11, j = i & 2047, r = j >> 4, s = j & 15;
        uint32_t dst = sb + (half ? STGL_O : STGH_O) + (uint32_t)r*(LDX*2) + s*16;
        const char* src = (half ? gl : gh) + (size_t)r*256 + s*16;
        asm volatile("cp.async.ca.shared.global [%0], [%1], 16;" :: "r"(dst), "l"(src));
    }
}

// write accum tile into X.  MODE 0: plain; 1: row-scale; 2: col-bias + relu
template<int MODE>
__device__ __forceinline__ void store_acc(uint8_t* smb, float (*acc)[4],
        const float* smf, int xo, int lane, int wr, int wc){
    const int g = lane >> 2, t = lane & 3;
#pragma unroll
    for (int mi = 0; mi < 2; mi++){
        int r0 = wr*32 + mi*16 + g;
#pragma unroll
        for (int ni = 0; ni < 4; ni++){
            int col = wc*32 + ni*8 + t*2;
            float* a = acc[mi*4 + ni];
            float v0 = a[0], v1 = a[1], v2 = a[2], v3 = a[3];
            if (MODE == 1){
                float s0 = smf[xo + r0], s1 = smf[xo + r0 + 8];
                v0 *= s0; v1 *= s0; v2 *= s1; v3 *= s1;
            }
            if (MODE == 2){
                float q0 = smf[xo + col], q1 = smf[xo + col + 1];
                v0 = fmaxf(v0 + q0, 0.0f); v1 = fmaxf(v1 + q1, 0.0f);
                v2 = fmaxf(v2 + q0, 0.0f); v3 = fmaxf(v3 + q1, 0.0f);
            }
            uint32_t h0,l0,h1,l1;
            split2(v0, v1, h0, l0);
            split2(v2, v3, h1, l1);
            uint32_t o0 = (uint32_t)(r0*LDX + col)*2, o1 = (uint32_t)((r0+8)*LDX + col)*2;
            *(uint32_t*)(smb + XH_O + o0) = h0;  *(uint32_t*)(smb + XL_O + o0) = l0;
            *(uint32_t*)(smb + XH_O + o1) = h1;  *(uint32_t*)(smb + XL_O + o1) = l1;
        }
    }
}

__device__ __forceinline__ void zero_acc(float (*acc)[4]){
#pragma unroll
    for (int i = 0; i < 8; i++)
#pragma unroll
        for (int j = 0; j < 4; j++) acc[i][j] = 0.0f;
}

__global__ __launch_bounds__(512)
void fused_kernel(const float* __restrict__ feat,
                  const float* __restrict__ b1, const float* __restrict__ b2,
                  const float* __restrict__ gamma, const float* __restrict__ beta,
                  float* __restrict__ out){
    extern __shared__ uint8_t smb[];
    float* smf = (float*)smb;
    const uint32_t sb = smem_u32(smb);
    const int tid = threadIdx.x, wid = tid >> 5, lane = tid & 31;
    const int wr = wid & 3, wc = wid >> 2;
    const int bw = blockIdx.x, b = bw / TWw, tw = bw % TWw;
    const size_t bt0 = (size_t)(b*Tt + tw);

    if (tid < 128){
        smf[B1_O/4 + tid] = b1[tid];
        smf[B2_O/4 + tid] = b2[tid];
        smf[GM_O/4 + tid] = gamma[tid];
        smf[BT_O/4 + tid] = beta[tid];
        int pb = (int)bt0*128 + tid;
        smf[SV_O/4 + tid] = g_P[pb] + g_P[pb + 128] + g_P[pb + 256];
    }
    __syncthreads();

    // dis_j = deg>0 ? rsqrt(max(deg,1e-38)) : 0
    {
        float4 s4 = ((const float4*)(smf + SV_O/4))[lane];
        const float* wwin = g_wf + bt0 * TILE;
        for (int j = wid; j < 384; j += 16){
            float4 v = ((const float4*)(wwin + (size_t)j*128))[lane];
            float p = v.x*s4.x + v.y*s4.y + v.z*s4.z + v.w*s4.w;
#pragma unroll
            for (int off = 16; off; off >>= 1) p += __shfl_xor_sync(0xffffffffu, p, off);
            if (lane == 0) smf[DIS_O/4 + j] = (p > 0.0f) ? rsqrtf(fmaxf(p, 1e-38f)) : 0.0f;
        }
    }
    __syncthreads();

    float acc[8][4];

    // ---------------- Stage C: Mt[d2][d1] = sum_j feat[j][d2] dis_j wf[j][d1]
    zero_acc(acc);
    for (int t2 = 0; t2 < 3; t2++){
        if (t2) __syncthreads();       // STG + X consumed by previous round
        stage_full(sb, g_fTh + (bt0 + t2)*TILE, g_fTl + (bt0 + t2)*TILE, tid);
        CP_COMMIT();
        // B = dis-scaled wfT -> X region (overlaps cp.async)
        {
            const float* wfTp = g_wfT + (bt0 + t2)*TILE;
            for (int i = tid; i < 8192; i += 512){
                int r = i >> 6, q = i & 63;
                int n0 = q*2;
                float2 v = *(const float2*)(wfTp + (size_t)r*128 + n0);
                float d0 = smf[DIS_O/4 + t2*128 + n0];
                float d1 = smf[DIS_O/4 + t2*128 + n0 + 1];
                uint32_t h, l;
                split2(v.x*d0, v.y*d1, h, l);
                uint32_t o = (uint32_t)(r*LDX + n0)*2;
                *(uint32_t*)(smb + XH_O + o) = h;
                *(uint32_t*)(smb + XL_O + o) = l;
            }
        }
        CP_WAIT0();
        __syncthreads();
#pragma unroll
        for (int k = 0; k < 8; k++)
            mma_k16(sb, STGH_O, STGL_O, k*16, XH_O, XL_O, k*16, acc, lane, wr, wc);
    }
    __syncthreads();
    // stage wf2 blob early (STG free), overlap with Mt store
    stage_full(sb, g_wfh + (bt0 + 2)*TILE, g_wfl + (bt0 + 2)*TILE, tid);
    CP_COMMIT();
    store_acc<0>(smb, acc, smf, 0, lane, wr, wc);          // X <- Mt
    CP_WAIT0();
    __syncthreads();

    // ---------------- Stage D: agg[n][d2] = sum_d1 wf2[n][d1] * Mt[d2][d1]
    zero_acc(acc);
#pragma unroll
    for (int k = 0; k < 8; k++)
        mma_k16(sb, STGH_O, STGL_O, k*16, XH_O, XL_O, k*16, acc, lane, wr, wc);
    __syncthreads();
    stage_full(sb, g_W1h, g_W1l, tid);
    CP_COMMIT();
    store_acc<1>(smb, acc, smf, DIS_O/4 + 256, lane, wr, wc);   // X <- dis2*agg
    CP_WAIT0();
    __syncthreads();

    // ---------------- Stage E: t1 = relu(aggS @ W1 + b1)
    zero_acc(acc);
#pragma unroll
    for (int k = 0; k < 8; k++)
        mma_k16(sb, XH_O, XL_O, k*16, STGH_O, STGL_O, k*16, acc, lane, wr, wc);
    __syncthreads();
    stage_full(sb, g_W2h, g_W2l, tid);
    CP_COMMIT();
    store_acc<2>(smb, acc, smf, B1_O/4, lane, wr, wc);          // X <- t1
    CP_WAIT0();
    __syncthreads();

    // ---------------- Stage F: t2 = t1 @ W2
    zero_acc(acc);
#pragma unroll
    for (int k = 0; k < 8; k++)
        mma_k16(sb, XH_O, XL_O, k*16, STGH_O, STGL_O, k*16, acc, lane, wr, wc);

    // ---------------- Epilogue: +b2 +feat, LayerNorm, store
    {
        const int g = lane >> 2, t = lane & 3;
        const float* featLast = feat + (bt0 + 2)*TILE;
#pragma unroll
        for (int mi = 0; mi < 2; mi++){
            int r0 = wr*32 + mi*16 + g;
            float s0 = 0.0f, q0 = 0.0f, s1 = 0.0f, q1 = 0.0f;
#pragma unroll
            for (int ni = 0; ni < 4; ni++){
                int col = wc*32 + ni*8 + t*2;
                float* a = acc[mi*4 + ni];
                float bb0 = smf[B2_O/4 + col], bb1 = smf[B2_O/4 + col + 1];
                float2 f0 = *(const float2*)(featLast + r0*128 + col);
                float2 f1 = *(const float2*)(featLast + (r0+8)*128 + col);
                a[0] += bb0 + f0.x; a[1] += bb1 + f0.y;
                a[2] += bb0 + f1.x; a[3] += bb1 + f1.y;
                s0 += a[0] + a[1];  q0 += a[0]*a[0] + a[1]*a[1];
                s1 += a[2] + a[3];  q1 += a[2]*a[2] + a[3]*a[3];
            }
            s0 += __shfl_xor_sync(0xffffffffu, s0, 1); s0 += __shfl_xor_sync(0xffffffffu, s0, 2);
            q0 += __shfl_xor_sync(0xffffffffu, q0, 1); q0 += __shfl_xor_sync(0xffffffffu, q0, 2);
            s1 += __shfl_xor_sync(0xffffffffu, s1, 1); s1 += __shfl_xor_sync(0xffffffffu, s1, 2);
            q1 += __shfl_xor_sync(0xffffffffu, q1, 1); q1 += __shfl_xor_sync(0xffffffffu, q1, 2);
            if (t == 0){
                smf[PSS_O/4 + r0*4 + wc] = s0;       smf[PSQ_O/4 + r0*4 + wc] = q0;
                smf[PSS_O/4 + (r0+8)*4 + wc] = s1;   smf[PSQ_O/4 + (r0+8)*4 + wc] = q1;
            }
        }
        __syncthreads();
        float* outp = out + (size_t)(b*TWw + tw)*TILE;
#pragma unroll
        for (int mi = 0; mi < 2; mi++){
            int r0 = wr*32 + mi*16 + g;
            float S0 = smf[PSS_O/4 + r0*4] + smf[PSS_O/4 + r0*4 + 1]
                     + smf[PSS_O/4 + r0*4 + 2] + smf[PSS_O/4 + r0*4 + 3];
            float Q0 = smf[PSQ_O/4 + r0*4] + smf[PSQ_O/4 + r0*4 + 1]
                     + smf[PSQ_O/4 + r0*4 + 2] + smf[PSQ_O/4 + r0*4 + 3];
            float S1 = smf[PSS_O/4 + (r0+8)*4] + smf[PSS_O/4 + (r0+8)*4 + 1]
                     + smf[PSS_O/4 + (r0+8)*4 + 2] + smf[PSS_O/4 + (r0+8)*4 + 3];
            float Q1 = smf[PSQ_O/4 + (r0+8)*4] + smf[PSQ_O/4 + (r0+8)*4 + 1]
                     + smf[PSQ_O/4 + (r0+8)*4 + 2] + smf[PSQ_O/4 + (r0+8)*4 + 3];
            float mu0 = S0 * 0.0078125f, mu1 = S1 * 0.0078125f;
            float rs0 = rsqrtf(Q0*0.0078125f - mu0*mu0 + 1e-5f);
            float rs1 = rsqrtf(Q1*0.0078125f - mu1*mu1 + 1e-5f);
#pragma unroll
            for (int ni = 0; ni < 4; ni++){
                int col = wc*32 + ni*8 + t*2;
                float* a = acc[mi*4 + ni];
                float gm0 = smf[GM_O/4 + col], gm1 = smf[GM_O/4 + col + 1];
                float bt0v = smf[BT_O/4 + col], bt1v = smf[BT_O/4 + col + 1];
                float2 o0, o1;
                o0.x = (a[0] - mu0)*rs0*gm0 + bt0v;
                o0.y = (a[1] - mu0)*rs0*gm1 + bt1v;
                o1.x = (a[2] - mu1)*rs1*gm0 + bt0v;
                o1.y = (a[3] - mu1)*rs1*gm1 + bt1v;
                *(float2*)(outp + r0*128 + col)     = o0;
                *(float2*)(outp + (r0+8)*128 + col) = o1;
            }
        }
    }
}

// ---------------------------------------------------------------------------
extern "C" void kernel_launch(void* const* d_in, const int* in_sizes, int n_in,
                              void* d_out, int out_size) {
    const float* feat  = (const float*)d_in[0];
    const float* w     = (const float*)d_in[1];
    const float* W1    = (const float*)d_in[2];
    const float* b1    = (const float*)d_in[3];
    const float* W2    = (const float*)d_in[4];
    const float* b2    = (const float*)d_in[5];
    const float* gamma = (const float*)d_in[6];
    const float* beta  = (const float*)d_in[7];
    float* out = (float*)d_out;

    cudaFuncSetAttribute(fused_kernel, cudaFuncAttributeMaxDynamicSharedMemorySize,
                         FUSED_SMEM);

    wf_kernel<<<NBT*16, 256>>>(feat, w);
    trans_kernel<<<NBT*4 + 8, 256>>>(feat, W1, W2);
    fused_kernel<<<Bn*TWw, 512, FUSED_SMEM>>>(feat, b1, b2, gamma, beta, out);
}

// round 7
// speedup vs baseline: 2.1063x; 1.1403x over previous
#include <cuda_runtime.h>
#include <cuda_bf16.h>
#include <cstdint>

#define Bn 8
#define Tt 64
#define TWw 62
#define NBT (Bn*Tt)
#define TILE 16384
#define NWIN (Bn*TWw)
#define GRID 148

// ---------------- device scratch ----------------
__device__ float g_wf [(size_t)NBT*TILE];      // wf fp32 [bt][n][d]
__device__ float g_wfT[(size_t)NBT*TILE];      // wf fp32 [bt][d][n]
__device__ float g_P  [NBT*128];
__device__ float g_DIS[NBT*3*128];             // [bt][role][j]
__device__ unsigned short g_wfh[(size_t)NBT*TILE], g_wfl[(size_t)NBT*TILE]; // wf bf16 [n][d]
__device__ unsigned short g_fTh[(size_t)NBT*TILE], g_fTl[(size_t)NBT*TILE]; // featT bf16 [d][n]
__device__ unsigned short g_W1h[TILE], g_W1l[TILE];   // W1T [h][i]
__device__ unsigned short g_W2h[TILE], g_W2l[TILE];   // W2T [o][i]

// ---------------- helpers ----------------
__device__ __forceinline__ uint32_t smem_u32(const void* p){
    uint32_t a;
    asm("{ .reg .u64 t; cvta.to.shared.u64 t, %1; cvt.u32.u64 %0, t; }" : "=r"(a) : "l"(p));
    return a;
}
__device__ __forceinline__ void ldsm4(uint32_t addr, uint32_t r[4]){
    asm volatile("ldmatrix.sync.aligned.m8n8.x4.shared.b16 {%0,%1,%2,%3}, [%4];"
        : "=r"(r[0]), "=r"(r[1]), "=r"(r[2]), "=r"(r[3]) : "r"(addr));
}
__device__ __forceinline__ void mma16816(float* c, const uint32_t a[4], uint32_t b0, uint32_t b1){
    asm volatile("mma.sync.aligned.m16n8k16.row.col.f32.bf16.bf16.f32 "
        "{%0,%1,%2,%3}, {%4,%5,%6,%7}, {%8,%9}, {%0,%1,%2,%3};"
        : "+f"(c[0]), "+f"(c[1]), "+f"(c[2]), "+f"(c[3])
        : "r"(a[0]), "r"(a[1]), "r"(a[2]), "r"(a[3]), "r"(b0), "r"(b1));
}
__device__ __forceinline__ void split2(float a, float b, uint32_t& hw, uint32_t& lw){
    __nv_bfloat16 ah = __float2bfloat16(a);
    __nv_bfloat16 bh = __float2bfloat16(b);
    __nv_bfloat16 al = __float2bfloat16(a - __bfloat162float(ah));
    __nv_bfloat16 bl = __float2bfloat16(b - __bfloat162float(bh));
    hw = (uint32_t)__bfloat16_as_ushort(ah) | ((uint32_t)__bfloat16_as_ushort(bh) << 16);
    lw = (uint32_t)__bfloat16_as_ushort(al) | ((uint32_t)__bfloat16_as_ushort(bl) << 16);
}
#define CP_COMMIT() asm volatile("cp.async.commit_group;" ::: "memory")
#define CP_WAIT0()  asm volatile("cp.async.wait_group 0;" ::: "memory")

// ===========================================================================
// Kernel 1: wf rows + bf16 hi/lo blob
// ===========================================================================
__global__ __launch_bounds__(256) void wf_kernel(const float* __restrict__ feat,
                                                 const float* __restrict__ w){
    __shared__ float sigw[128];
    int tid = threadIdx.x;
    if (tid < 128) sigw[tid] = 1.0f / (1.0f + expf(-w[tid]));
    __syncthreads();
    int warp = tid >> 5, lane = tid & 31;
    size_t row = (size_t)blockIdx.x * 8 + warp;
    float4 v = ((const float4*)(feat + row * 128))[lane];
    float4 sw = ((const float4*)sigw)[lane];
    v.x *= sw.x; v.y *= sw.y; v.z *= sw.z; v.w *= sw.w;
    float sq = v.x*v.x + v.y*v.y + v.z*v.z + v.w*v.w;
#pragma unroll
    for (int off = 16; off; off >>= 1) sq += __shfl_xor_sync(0xffffffffu, sq, off);
    float sc = 1.0f / fmaxf(sqrtf(sq), 1e-12f);
    v.x *= sc; v.y *= sc; v.z *= sc; v.w *= sc;
    ((float4*)(g_wf + row * 128))[lane] = v;
    uint32_t h0,l0,h1,l1;
    split2(v.x, v.y, h0, l0);
    split2(v.z, v.w, h1, l1);
    size_t bi = row*64 + lane*2;
    ((uint32_t*)g_wfh)[bi]   = h0;  ((uint32_t*)g_wfl)[bi]   = l0;
    ((uint32_t*)g_wfh)[bi+1] = h1;  ((uint32_t*)g_wfl)[bi+1] = l1;
}

// ===========================================================================
// Kernel 2: transposes + P sums
// ===========================================================================
__global__ __launch_bounds__(256) void trans_kernel(const float* __restrict__ feat,
                                                    const float* __restrict__ W1,
                                                    const float* __restrict__ W2){
    __shared__ float ft[128*33];
    __shared__ float wt[128*33];
    __shared__ float pp[8*32];
    const int tid = threadIdx.x, blk = blockIdx.x;
    const bool isBT = blk < NBT*4;
    int bt = 0, dc;
    const float *S0, *S1 = nullptr;
    unsigned short *oh, *ol;
    if (isBT){
        bt = blk >> 2; dc = blk & 3;
        S0 = feat + (size_t)bt*TILE;
        S1 = g_wf + (size_t)bt*TILE;
        oh = g_fTh + (size_t)bt*TILE;
        ol = g_fTl + (size_t)bt*TILE;
    } else {
        int k = blk - NBT*4;
        int which = k >> 2; dc = k & 3;
        S0 = which ? W2 : W1;
        oh = which ? g_W2h : g_W1h;
        ol = which ? g_W2l : g_W1l;
    }
    for (int i = tid; i < 1024; i += 256){
        int r = i >> 3, s = i & 7;
        float4 v = *(const float4*)(S0 + (size_t)r*128 + dc*32 + s*4);
        ft[r*33 + s*4    ] = v.x; ft[r*33 + s*4 + 1] = v.y;
        ft[r*33 + s*4 + 2] = v.z; ft[r*33 + s*4 + 3] = v.w;
        if (isBT){
            float4 u = *(const float4*)(S1 + (size_t)r*128 + dc*32 + s*4);
            wt[r*33 + s*4    ] = u.x; wt[r*33 + s*4 + 1] = u.y;
            wt[r*33 + s*4 + 2] = u.z; wt[r*33 + s*4 + 3] = u.w;
        }
    }
    __syncthreads();
    if (isBT){
        int part = tid >> 5, d = tid & 31;
        float s = 0.0f;
        for (int n = part*16; n < part*16 + 16; n++) s += wt[n*33 + d];
        pp[part*32 + d] = s;
    }
    for (int i = tid; i < 2048; i += 256){
        int d = i >> 6, q = i & 63, n0 = q*2;
        uint32_t h, l;
        split2(ft[n0*33 + d], ft[(n0+1)*33 + d], h, l);
        size_t bi = (size_t)(dc*32 + d)*64 + q;
        ((uint32_t*)oh)[bi] = h;
        ((uint32_t*)ol)[bi] = l;
        if (isBT){
            float2 v2 = make_float2(wt[n0*33 + d], wt[(n0+1)*33 + d]);
            *(float2*)(g_wfT + (size_t)bt*TILE + (size_t)(dc*32 + d)*128 + n0) = v2;
        }
    }
    __syncthreads();
    if (isBT && tid < 32){
        float s = 0.0f;
#pragma unroll
        for (int p = 0; p < 8; p++) s += pp[p*32 + tid];
        g_P[bt*128 + dc*32 + tid] = s;
    }
}

// ===========================================================================
// Kernel 3: DIS[bt][role][j] = rsqrt(deg) precompute
//   deg for (timestep bt, role r, node j) = wf_j . (P[t-r] + P[t-r+1] + P[t-r+2])
// ===========================================================================
__global__ __launch_bounds__(256) void deg_kernel(){
    __shared__ float P5[5][128];
    const int bt = blockIdx.x, b = bt >> 6, t = bt & 63;
    const int tid = threadIdx.x, wid = tid >> 5, lane = tid & 31;
    for (int i = tid; i < 640; i += 256){
        int dl = i >> 7, d = i & 127;
        int tt = t + dl - 2;
        P5[dl][d] = (tt >= 0 && tt < 64) ? g_P[(b*64 + tt)*128 + d] : 0.0f;
    }
    __syncthreads();
    const float* wfp = g_wf + (size_t)bt*TILE;
    for (int j = wid; j < 128; j += 8){
        float4 v = ((const float4*)(wfp + (size_t)j*128))[lane];
        float q[5];
#pragma unroll
        for (int dl = 0; dl < 5; dl++){
            float4 p = ((const float4*)P5[dl])[lane];
            q[dl] = v.x*p.x + v.y*p.y + v.z*p.z + v.w*p.w;
        }
#pragma unroll
        for (int off = 16; off; off >>= 1)
#pragma unroll
            for (int dl = 0; dl < 5; dl++) q[dl] += __shfl_xor_sync(0xffffffffu, q[dl], off);
        if (lane == 0){
#pragma unroll
            for (int r = 0; r < 3; r++){
                int tw = t - r;
                if (tw >= 0 && tw <= 61){
                    float deg = q[2-r] + q[3-r] + q[4-r];
                    g_DIS[(bt*3 + r)*128 + j] = (deg > 0.0f) ? rsqrtf(fmaxf(deg, 1e-38f)) : 0.0f;
                }
            }
        }
    }
}

// ===========================================================================
// Fused per-window kernel: persistent, 512 threads, cross-window prefetch
// ===========================================================================
#define STGH_O 0
#define STGL_O 34816
#define XH_O   69632
#define XL_O   104448
#define DIS_O  139264
#define B1_O   140800
#define B2_O   141312
#define GM_O   141824
#define BT_O   142336
#define PSS_O  143360
#define PSQ_O  145408
#define FUSED_SMEM 147456

#define LDX 136

__device__ __forceinline__ void mma_k16(uint32_t sb,
        uint32_t aH, uint32_t aL, int ka0,
        uint32_t bH, uint32_t bL, int kb0,
        float (*acc)[4], int lane, int wr, int wc){
    const int arow = lane & 15, chalf = (lane >> 4) << 3;
    uint32_t Ah[2][4], Al[2][4];
#pragma unroll
    for (int mi = 0; mi < 2; mi++){
        uint32_t off = (uint32_t)((wr*32 + mi*16 + arow) * LDX + ka0 + chalf) * 2;
        ldsm4(sb + aH + off, Ah[mi]);
        ldsm4(sb + aL + off, Al[mi]);
    }
#pragma unroll
    for (int ng = 0; ng < 2; ng++){
        uint32_t off = (uint32_t)((wc*32 + ng*16 + arow) * LDX + kb0 + chalf) * 2;
        uint32_t Bh[4], Bl[4];
        ldsm4(sb + bH + off, Bh);
        ldsm4(sb + bL + off, Bl);
#pragma unroll
        for (int mi = 0; mi < 2; mi++){
            float* c0 = acc[mi*4 + ng*2];
            float* c1 = acc[mi*4 + ng*2 + 1];
            mma16816(c0, Ah[mi], Bh[0], Bh[2]);
            mma16816(c0, Ah[mi], Bl[0], Bl[2]);
            mma16816(c0, Al[mi], Bh[0], Bh[2]);
            mma16816(c1, Ah[mi], Bh[1], Bh[3]);
            mma16816(c1, Ah[mi], Bl[1], Bl[3]);
            mma16816(c1, Al[mi], Bh[1], Bh[3]);
        }
    }
}

__device__ __forceinline__ void stage_full(uint32_t sb,
        const unsigned short* __restrict__ sh, const unsigned short* __restrict__ sl,
        int tid){
    const char* gh = (const char*)sh;
    const char* gl = (const char*)sl;
    for (int i = tid; i < 4096; i += 512){
        int half = i >> 11, j = i & 2047, r = j >> 4, s = j & 15;
        uint32_t dst = sb + (half ? STGL_O : STGH_O) + (uint32_t)r*(LDX*2) + s*16;
        const char* src = (half ? gl : gh) + (size_t)r*256 + s*16;
        asm volatile("cp.async.ca.shared.global [%0], [%1], 16;" :: "r"(dst), "l"(src));
    }
}

template<int MODE>
__device__ __forceinline__ void store_acc(uint8_t* smb, float (*acc)[4],
        const float* smf, int xo, int lane, int wr, int wc){
    const int g = lane >> 2, t = lane & 3;
#pragma unroll
    for (int mi = 0; mi < 2; mi++){
        int r0 = wr*32 + mi*16 + g;
#pragma unroll
        for (int ni = 0; ni < 4; ni++){
            int col = wc*32 + ni*8 + t*2;
            float* a = acc[mi*4 + ni];
            float v0 = a[0], v1 = a[1], v2 = a[2], v3 = a[3];
            if (MODE == 1){
                float s0 = smf[xo + r0], s1 = smf[xo + r0 + 8];
                v0 *= s0; v1 *= s0; v2 *= s1; v3 *= s1;
            }
            if (MODE == 2){
                float q0 = smf[xo + col], q1 = smf[xo + col + 1];
                v0 = fmaxf(v0 + q0, 0.0f); v1 = fmaxf(v1 + q1, 0.0f);
                v2 = fmaxf(v2 + q0, 0.0f); v3 = fmaxf(v3 + q1, 0.0f);
            }
            uint32_t h0,l0,h1,l1;
            split2(v0, v1, h0, l0);
            split2(v2, v3, h1, l1);
            uint32_t o0 = (uint32_t)(r0*LDX + col)*2, o1 = (uint32_t)((r0+8)*LDX + col)*2;
            *(uint32_t*)(smb + XH_O + o0) = h0;  *(uint32_t*)(smb + XL_O + o0) = l0;
            *(uint32_t*)(smb + XH_O + o1) = h1;  *(uint32_t*)(smb + XL_O + o1) = l1;
        }
    }
}

__device__ __forceinline__ void zero_acc(float (*acc)[4]){
#pragma unroll
    for (int i = 0; i < 8; i++)
#pragma unroll
        for (int j = 0; j < 4; j++) acc[i][j] = 0.0f;
}

__global__ __launch_bounds__(512)
void fused_kernel(const float* __restrict__ feat,
                  const float* __restrict__ b1, const float* __restrict__ b2,
                  const float* __restrict__ gamma, const float* __restrict__ beta,
                  float* __restrict__ out){
    extern __shared__ uint8_t smb[];
    float* smf = (float*)smb;
    const uint32_t sb = smem_u32(smb);
    const int tid = threadIdx.x, wid = tid >> 5, lane = tid & 31;
    const int wr = wid & 3, wc = wid >> 2;

    if (tid < 128){
        smf[B1_O/4 + tid] = b1[tid];
        smf[B2_O/4 + tid] = b2[tid];
        smf[GM_O/4 + tid] = gamma[tid];
        smf[BT_O/4 + tid] = beta[tid];
    }

    bool prefetched = false;
    for (int bw = blockIdx.x; bw < NWIN; bw += GRID){
        const int b = bw / TWw, tw = bw % TWw;
        const size_t bt0 = (size_t)(b*Tt + tw);
        if (tid < 128) smf[DIS_O/4 + tid] = g_DIS[(bt0 + 2)*384 + 256 + tid];
        __syncthreads();

        float acc[8][4];

        // ---- Stage C: Mt[d2][d1] = sum_j feat[j][d2] dis_j wf[j][d1]
        zero_acc(acc);
        for (int t2 = 0; t2 < 3; t2++){
            if (t2) __syncthreads();
            if (t2 || !prefetched){
                stage_full(sb, g_fTh + (bt0 + t2)*TILE, g_fTl + (bt0 + t2)*TILE, tid);
                CP_COMMIT();
            }
            {   // B = dis-scaled wfT -> X (overlaps cp.async)
                const float* wfTp = g_wfT + (bt0 + t2)*TILE;
                const float2* disp = (const float2*)(g_DIS + ((bt0 + t2)*3 + t2)*128);
                for (int i = tid; i < 8192; i += 512){
                    int r = i >> 6, q = i & 63;
                    int n0 = q*2;
                    float2 v = *(const float2*)(wfTp + (size_t)r*128 + n0);
                    float2 dd = disp[q];
                    uint32_t h, l;
                    split2(v.x*dd.x, v.y*dd.y, h, l);
                    uint32_t o = (uint32_t)(r*LDX + n0)*2;
                    *(uint32_t*)(smb + XH_O + o) = h;
                    *(uint32_t*)(smb + XL_O + o) = l;
                }
            }
            CP_WAIT0();
            __syncthreads();
#pragma unroll
            for (int k = 0; k < 8; k++)
                mma_k16(sb, STGH_O, STGL_O, k*16, XH_O, XL_O, k*16, acc, lane, wr, wc);
        }
        __syncthreads();
        stage_full(sb, g_wfh + (bt0 + 2)*TILE, g_wfl + (bt0 + 2)*TILE, tid);
        CP_COMMIT();
        store_acc<0>(smb, acc, smf, 0, lane, wr, wc);          // X <- Mt
        CP_WAIT0();
        __syncthreads();

        // ---- Stage D: agg[n][d2]
        zero_acc(acc);
#pragma unroll
        for (int k = 0; k < 8; k++)
            mma_k16(sb, STGH_O, STGL_O, k*16, XH_O, XL_O, k*16, acc, lane, wr, wc);
        __syncthreads();
        stage_full(sb, g_W1h, g_W1l, tid);
        CP_COMMIT();
        store_acc<1>(smb, acc, smf, DIS_O/4, lane, wr, wc);    // X <- dis2*agg
        CP_WAIT0();
        __syncthreads();

        // ---- Stage E: t1 = relu(aggS @ W1 + b1)
        zero_acc(acc);
#pragma unroll
        for (int k = 0; k < 8; k++)
            mma_k16(sb, XH_O, XL_O, k*16, STGH_O, STGL_O, k*16, acc, lane, wr, wc);
        __syncthreads();
        stage_full(sb, g_W2h, g_W2l, tid);
        CP_COMMIT();
        store_acc<2>(smb, acc, smf, B1_O/4, lane, wr, wc);     // X <- t1
        CP_WAIT0();
        __syncthreads();

        // ---- Stage F: t2 = t1 @ W2
        zero_acc(acc);
#pragma unroll
        for (int k = 0; k < 8; k++)
            mma_k16(sb, XH_O, XL_O, k*16, STGH_O, STGL_O, k*16, acc, lane, wr, wc);
        __syncthreads();

        // ---- prefetch next window's first blob (hidden under epilogue)
        int nbw = bw + GRID;
        prefetched = (nbw < NWIN);
        if (prefetched){
            size_t nbt0 = (size_t)((nbw / TWw)*Tt + (nbw % TWw));
            stage_full(sb, g_fTh + nbt0*TILE, g_fTl + nbt0*TILE, tid);
            CP_COMMIT();
        }

        // ---- Epilogue: +b2 +feat, LayerNorm, store
        {
            const int g = lane >> 2, t = lane & 3;
            const float* featLast = feat + (bt0 + 2)*TILE;
#pragma unroll
            for (int mi = 0; mi < 2; mi++){
                int r0 = wr*32 + mi*16 + g;
                float s0 = 0.0f, q0 = 0.0f, s1 = 0.0f, q1 = 0.0f;
#pragma unroll
                for (int ni = 0; ni < 4; ni++){
                    int col = wc*32 + ni*8 + t*2;
                    float* a = acc[mi*4 + ni];
                    float bb0 = smf[B2_O/4 + col], bb1 = smf[B2_O/4 + col + 1];
                    float2 f0 = *(const float2*)(featLast + r0*128 + col);
                    float2 f1 = *(const float2*)(featLast + (r0+8)*128 + col);
                    a[0] += bb0 + f0.x; a[1] += bb1 + f0.y;
                    a[2] += bb0 + f1.x; a[3] += bb1 + f1.y;
                    s0 += a[0] + a[1];  q0 += a[0]*a[0] + a[1]*a[1];
                    s1 += a[2] + a[3];  q1 += a[2]*a[2] + a[3]*a[3];
                }
                s0 += __shfl_xor_sync(0xffffffffu, s0, 1); s0 += __shfl_xor_sync(0xffffffffu, s0, 2);
                q0 += __shfl_xor_sync(0xffffffffu, q0, 1); q0 += __shfl_xor_sync(0xffffffffu, q0, 2);
                s1 += __shfl_xor_sync(0xffffffffu, s1, 1); s1 += __shfl_xor_sync(0xffffffffu, s1, 2);
                q1 += __shfl_xor_sync(0xffffffffu, q1, 1); q1 += __shfl_xor_sync(0xffffffffu, q1, 2);
                if (t == 0){
                    smf[PSS_O/4 + r0*4 + wc] = s0;       smf[PSQ_O/4 + r0*4 + wc] = q0;
                    smf[PSS_O/4 + (r0+8)*4 + wc] = s1;   smf[PSQ_O/4 + (r0+8)*4 + wc] = q1;
                }
            }
            __syncthreads();
            float* outp = out + (size_t)(b*TWw + tw)*TILE;
#pragma unroll
            for (int mi = 0; mi < 2; mi++){
                int r0 = wr*32 + mi*16 + g;
                float S0 = smf[PSS_O/4 + r0*4] + smf[PSS_O/4 + r0*4 + 1]
                         + smf[PSS_O/4 + r0*4 + 2] + smf[PSS_O/4 + r0*4 + 3];
                float Q0 = smf[PSQ_O/4 + r0*4] + smf[PSQ_O/4 + r0*4 + 1]
                         + smf[PSQ_O/4 + r0*4 + 2] + smf[PSQ_O/4 + r0*4 + 3];
                float S1 = smf[PSS_O/4 + (r0+8)*4] + smf[PSS_O/4 + (r0+8)*4 + 1]
                         + smf[PSS_O/4 + (r0+8)*4 + 2] + smf[PSS_O/4 + (r0+8)*4 + 3];
                float Q1 = smf[PSQ_O/4 + (r0+8)*4] + smf[PSQ_O/4 + (r0+8)*4 + 1]
                         + smf[PSQ_O/4 + (r0+8)*4 + 2] + smf[PSQ_O/4 + (r0+8)*4 + 3];
                float mu0 = S0 * 0.0078125f, mu1 = S1 * 0.0078125f;
                float rs0 = rsqrtf(Q0*0.0078125f - mu0*mu0 + 1e-5f);
                float rs1 = rsqrtf(Q1*0.0078125f - mu1*mu1 + 1e-5f);
#pragma unroll
                for (int ni = 0; ni < 4; ni++){
                    int col = wc*32 + ni*8 + t*2;
                    float* a = acc[mi*4 + ni];
                    float gm0 = smf[GM_O/4 + col], gm1 = smf[GM_O/4 + col + 1];
                    float bt0v = smf[BT_O/4 + col], bt1v = smf[BT_O/4 + col + 1];
                    float2 o0, o1;
                    o0.x = (a[0] - mu0)*rs0*gm0 + bt0v;
                    o0.y = (a[1] - mu0)*rs0*gm1 + bt1v;
                    o1.x = (a[2] - mu1)*rs1*gm0 + bt0v;
                    o1.y = (a[3] - mu1)*rs1*gm1 + bt1v;
                    *(float2*)(outp + r0*128 + col)     = o0;
                    *(float2*)(outp + (r0+8)*128 + col) = o1;
                }
            }
        }
        __syncthreads();
    }
}

// ---------------------------------------------------------------------------
extern "C" void kernel_launch(void* const* d_in, const int* in_sizes, int n_in,
                              void* d_out, int out_size) {
    const float* feat  = (const float*)d_in[0];
    const float* w     = (const float*)d_in[1];
    const float* W1    = (const float*)d_in[2];
    const float* b1    = (const float*)d_in[3];
    const float* W2    = (const float*)d_in[4];
    const float* b2    = (const float*)d_in[5];
    const float* gamma = (const float*)d_in[6];
    const float* beta  = (const float*)d_in[7];
    float* out = (float*)d_out;

    cudaFuncSetAttribute(fused_kernel, cudaFuncAttributeMaxDynamicSharedMemorySize,
                         FUSED_SMEM);

    wf_kernel<<<NBT*16, 256>>>(feat, w);
    trans_kernel<<<NBT*4 + 8, 256>>>(feat, W1, W2);
    deg_kernel<<<NBT, 256>>>();
    fused_kernel<<<GRID, 512, FUSED_SMEM>>>(feat, b1, b2, gamma, beta, out);
}